// round 12
// baseline (speedup 1.0000x reference)
#include <cuda_runtime.h>

#define BATCH   32
#define NA      8732
#define NCLASS  91
#define NC      90
#define KTOP    400
#define NCAND   (NC * KTOP)      /* 36000 */
#define MAXDET  200
#define IMGSZ   300.0f
#define SCORE_T 0.01f
#define NMS_T   0.45f
#define BBOX_CLIP 4.135166556742356f
#define NEG_INF __int_as_float(0xff800000)
#define TAU_MIN 0xBC23D70Cu      /* fmono(0.01f)+1 : smallest passing key */

typedef unsigned long long u64;
typedef unsigned u32;

// -------- scratch (device globals; no allocations allowed) --------
__device__ float  d_probs[(size_t)BATCH * NC * NA];
__device__ float4 d_dboxes[(size_t)BATCH * NA];
// fast path
#define SEL_CAP 96
__device__ u64 d_selKey[(size_t)BATCH * NC * SEL_CAP];
__device__ int d_selN[BATCH * NC];
__device__ u32 d_capmax[BATCH];
__device__ int d_overflow[BATCH];
__device__ u64 d_fin[(size_t)BATCH * 9216];
__device__ int d_finN[BATCH];
__device__ int d_ok[BATCH];
// fallback path
__device__ float  d_candScore[(size_t)BATCH * NCAND];
__device__ int    d_candAnchor[(size_t)BATCH * NCAND];
__device__ float4 d_candBox[(size_t)BATCH * NCAND];

__device__ __forceinline__ u32 fmono(float f) {
    u32 u = __float_as_uint(f);
    return u ^ ((u >> 31) ? 0xFFFFFFFFu : 0x80000000u);
}

// ================= Kernel 1: softmax (XLA:GPU warp row-reduce order) + decode
// FROZEN FP ARITHMETIC for every value that can reach the output: exact
// __fdiv_rn for all p that might exceed 0.01. The rcp prefilter only skips
// divisions provably below threshold (|rcp path err| <= 1.8e-7 rel).
__global__ void __launch_bounds__(1024) k_softmax_decode(
        const float* __restrict__ logits,
        const float* __restrict__ reg,
        const float* __restrict__ anchors) {
    __shared__ float s_p[NC][33];
    int w = threadIdx.x >> 5, lane = threadIdx.x & 31;
    long flat = (long)blockIdx.x * 32 + w;
    size_t lbase = (size_t)flat * NCLASS;
    int b0 = (int)((blockIdx.x * 32) / NA);
    int a0 = (int)(blockIdx.x * 32 - b0 * NA);

    if (blockIdx.x == 0 && threadIdx.x < BATCH) {     // folded init
        d_capmax[threadIdx.x] = 0u; d_overflow[threadIdx.x] = 0;
        d_finN[threadIdx.x] = 0;    d_ok[threadIdx.x] = 0;
    }

    float x0 = logits[lbase + lane];
    float x1 = logits[lbase + lane + 32];
    float x2 = (lane < 27) ? logits[lbase + lane + 64] : NEG_INF;

    float m = fmaxf(fmaxf(x0, x1), x2);
    #pragma unroll
    for (int o = 16; o; o >>= 1) m = fmaxf(m, __shfl_down_sync(0xffffffffu, m, o));
    m = __shfl_sync(0xffffffffu, m, 0);

    float e0 = expf(x0 - m), e1 = expf(x1 - m), e2 = expf(x2 - m);
    float s = __fadd_rn(__fadd_rn(e0, e1), e2);
    #pragma unroll
    for (int o = 16; o; o >>= 1) s = __fadd_rn(s, __shfl_down_sync(0xffffffffu, s, o));
    s = __shfl_sync(0xffffffffu, s, 0);

    float rs = __frcp_rn(s);
    if (lane >= 1) {
        float p = (__fmul_rn(e0, rs) > 0.00999f) ? __fdiv_rn(e0, s) : NEG_INF;
        s_p[lane - 1][w] = (p > SCORE_T) ? p : NEG_INF;
    }
    {
        float p = (__fmul_rn(e1, rs) > 0.00999f) ? __fdiv_rn(e1, s) : NEG_INF;
        s_p[lane + 31][w] = (p > SCORE_T) ? p : NEG_INF;
    }
    if (lane < 27) {
        float p = (__fmul_rn(e2, rs) > 0.00999f) ? __fdiv_rn(e2, s) : NEG_INF;
        s_p[lane + 63][w] = (p > SCORE_T) ? p : NEG_INF;
    }
    __syncthreads();

    #pragma unroll
    for (int i = threadIdx.x; i < NC * 32; i += 1024) {
        int c = i >> 5, wl = i & 31;
        int a = a0 + wl, b = b0;
        if (a >= NA) { a -= NA; b++; }
        d_probs[((size_t)b * NC + c) * NA + a] = s_p[c][wl];
    }

    if (threadIdx.x < 32) {
        int a = a0 + threadIdx.x, b = b0;
        if (a >= NA) { a -= NA; b++; }
        long fl = (long)blockIdx.x * 32 + threadIdx.x;
        float4 rg = ((const float4*)reg)[fl];
        float4 an = ((const float4*)anchors)[a];
        float wa = __fsub_rn(an.z, an.x), ha = __fsub_rn(an.w, an.y);
        float cxa = __fadd_rn(an.x, __fmul_rn(0.5f, wa));
        float cya = __fadd_rn(an.y, __fmul_rn(0.5f, ha));
        float dx = __fdiv_rn(rg.x, 10.0f), dy = __fdiv_rn(rg.y, 10.0f);
        float dw = fminf(__fdiv_rn(rg.z, 5.0f), BBOX_CLIP);
        float dh = fminf(__fdiv_rn(rg.w, 5.0f), BBOX_CLIP);
        float cx = __fadd_rn(__fmul_rn(dx, wa), cxa);
        float cy = __fadd_rn(__fmul_rn(dy, ha), cya);
        float bw = __fmul_rn(expf(dw), wa), bh = __fmul_rn(expf(dh), ha);
        float hw = __fmul_rn(0.5f, bw), hh = __fmul_rn(0.5f, bh);
        float4 bx;
        bx.x = fminf(fmaxf(__fsub_rn(cx, hw), 0.f), IMGSZ);
        bx.y = fminf(fmaxf(__fsub_rn(cy, hh), 0.f), IMGSZ);
        bx.z = fminf(fmaxf(__fadd_rn(cx, hw), 0.f), IMGSZ);
        bx.w = fminf(fmaxf(__fadd_rn(cy, hh), 0.f), IMGSZ);
        d_dboxes[(size_t)b * NA + a] = bx;
    }
}

// ===== Kernel 2: per-(b,c) select all candidates >= tau_c (target 64..96) ====
// ANY tau is exactness-safe: capmax/overflow verification in k_out_fast
// covers truncation. Octary search only affects speed.
#define NLOC 18

__global__ void __launch_bounds__(512) k_selclass() {
    int bc = blockIdx.x;
    int b = bc / NC;
    const float* sc = &d_probs[(size_t)bc * NA];
    int t = threadIdx.x;

    u32 key[NLOC];
    #pragma unroll
    for (int j = 0; j < NLOC; j++) {
        int idx = j * 512 + t;
        float v = (idx < NA) ? sc[idx] : -1.0f;
        key[j] = (idx < NA && v > SCORE_T) ? fmono(v) : 0u;
    }

    __shared__ int s_cnt;
    __shared__ int s_n;
    __shared__ u64 s_h[2];

    if (t == 0) s_cnt = 0;
    __syncthreads();
    {
        int cl = 0;
        #pragma unroll
        for (int j = 0; j < NLOC; j++) cl += (key[j] >= TAU_MIN);
        #pragma unroll
        for (int o = 16; o; o >>= 1) cl += __shfl_down_sync(0xffffffffu, cl, o);
        if ((t & 31) == 0) atomicAdd(&s_cnt, cl);
    }
    __syncthreads();
    int cnt0 = s_cnt;
    __syncthreads();

    u32 tau = TAU_MIN;
    int capped = 0;
    if (cnt0 > SEL_CAP) {
        capped = 1;
        u32 lo = TAU_MIN + 1, hi = 0xBF800000u;
        while (lo <= hi) {
            if (hi - lo >= 64) {
                // ---- octary round: 7 thresholds q1..q7 ----
                u32 wdt = hi - lo;
                u32 q1 = lo + (u32)(((u64)wdt * 1) >> 3);
                u32 q2 = lo + (u32)(((u64)wdt * 2) >> 3);
                u32 q3 = lo + (u32)(((u64)wdt * 3) >> 3);
                u32 q4 = lo + (u32)(((u64)wdt * 4) >> 3);
                u32 q5 = lo + (u32)(((u64)wdt * 5) >> 3);
                u32 q6 = lo + (u32)(((u64)wdt * 6) >> 3);
                u32 q7 = lo + (u32)(((u64)wdt * 7) >> 3);
                if (t == 0) { s_h[0] = 0ull; s_h[1] = 0ull; }
                __syncthreads();
                u64 h0 = 0ull, h1 = 0ull;
                #pragma unroll
                for (int j = 0; j < NLOC; j++) {
                    u32 kk = key[j];
                    int pos;
                    if (kk >= q4) pos = (kk >= q6) ? ((kk >= q7) ? 7 : 6)
                                                   : ((kk >= q5) ? 5 : 4);
                    else          pos = (kk >= q2) ? ((kk >= q3) ? 3 : 2)
                                                   : ((kk >= q1) ? 1 : 0);
                    if (pos >= 4) h1 += 1ull << ((pos - 4) << 4);
                    else          h0 += 1ull << (pos << 4);
                }
                #pragma unroll
                for (int o = 16; o; o >>= 1) {
                    h0 += __shfl_down_sync(0xffffffffu, h0, o);
                    h1 += __shfl_down_sync(0xffffffffu, h1, o);
                }
                if ((t & 31) == 0) {
                    atomicAdd(&s_h[0], h0);
                    atomicAdd(&s_h[1], h1);
                }
                __syncthreads();
                u64 H0 = s_h[0], H1 = s_h[1];
                __syncthreads();
                int c7 = (int)((H1 >> 48) & 0xFFFF);
                int c6 = c7 + (int)((H1 >> 32) & 0xFFFF);
                int c5 = c6 + (int)((H1 >> 16) & 0xFFFF);
                int c4 = c5 + (int)(H1 & 0xFFFF);
                int c3 = c4 + (int)((H0 >> 48) & 0xFFFF);
                int c2 = c3 + (int)((H0 >> 32) & 0xFFFF);
                int c1 = c2 + (int)((H0 >> 16) & 0xFFFF);
                int ks, cks; u32 mtau, mnext; bool top = false;
                if      (c7 >= 64) { ks = 7; cks = c7; mtau = q7; mnext = 0; top = true; }
                else if (c6 >= 64) { ks = 6; cks = c6; mtau = q6; mnext = q7; }
                else if (c5 >= 64) { ks = 5; cks = c5; mtau = q5; mnext = q6; }
                else if (c4 >= 64) { ks = 4; cks = c4; mtau = q4; mnext = q5; }
                else if (c3 >= 64) { ks = 3; cks = c3; mtau = q3; mnext = q4; }
                else if (c2 >= 64) { ks = 2; cks = c2; mtau = q2; mnext = q3; }
                else if (c1 >= 64) { ks = 1; cks = c1; mtau = q1; mnext = q2; }
                else               { ks = 0; cks = 0;  mtau = 0;  mnext = 0; }
                if (ks >= 1) {
                    tau = mtau;
                    if (cks <= SEL_CAP) break;
                    lo = mtau + 1;
                    if (!top) hi = mnext - 1;
                } else {
                    hi = q1 - 1;
                }
            } else {
                // ---- binary tail round ----
                u32 mid = lo + ((hi - lo) >> 1);
                if (t == 0) s_cnt = 0;
                __syncthreads();
                int cl = 0;
                #pragma unroll
                for (int j = 0; j < NLOC; j++) cl += (key[j] >= mid);
                #pragma unroll
                for (int o = 16; o; o >>= 1) cl += __shfl_down_sync(0xffffffffu, cl, o);
                if ((t & 31) == 0) atomicAdd(&s_cnt, cl);
                __syncthreads();
                int cn = s_cnt;
                __syncthreads();
                if (cn >= 64) {
                    tau = mid; lo = mid + 1;
                    if (cn <= SEL_CAP) break;
                } else hi = mid - 1;
            }
        }
    }

    if (t == 0) s_n = 0;
    __syncthreads();
    #pragma unroll
    for (int j = 0; j < NLOC; j++) {
        if (key[j] >= tau) {
            int p = atomicAdd(&s_n, 1);
            if (p < SEL_CAP) {
                u32 anchor = (u32)(j * 512 + t);
                d_selKey[(size_t)bc * SEL_CAP + p] =
                    ((u64)key[j] << 14) | (u64)(0x3FFFu - anchor);
            }
        }
    }
    __syncthreads();
    if (t == 0) {
        int n = s_n;
        d_selN[bc] = (n < SEL_CAP) ? n : SEL_CAP;
        if (n > SEL_CAP) d_overflow[b] = 1;
        if (capped) atomicMax(&d_capmax[b], tau);
    }
}

// ---- warp-register bitonic helpers (128 u64, 4/lane, descending) ----
__device__ __forceinline__ u64 ce_shfl(u64 x, int j2, bool dird, int lane) {
    u64 y = __shfl_xor_sync(0xffffffffu, x, j2);
    bool lower = (lane & j2) == 0;
    bool keepmax = (dird == lower);
    u64 mx = (x > y) ? x : y;
    u64 mn = (x > y) ? y : x;
    return keepmax ? mx : mn;
}

// ===== Kernel 3: warp-sort<=128 + ballot-parallel greedy NMS =====
__global__ void __launch_bounds__(128) k_nms_fast() {
    int bc = blockIdx.x;
    int b = bc / NC, c = bc % NC;
    int n = d_selN[bc];
    if (n == 0) return;
    int t = threadIdx.x;
    int wid = t >> 5, lane = t & 31;

    __shared__ u64   s_key[128];
    __shared__ float4 s_bx[SEL_CAP];
    __shared__ float  s_ar[SEL_CAP];
    __shared__ u64   s_m0[SEL_CAP], s_m1[SEL_CAP];
    __shared__ u64   s_alive[2], s_hk[2];

    if (t < 2) { s_alive[t] = 0ull; s_hk[t] = 0ull; }

    if (t < 32) {
        u64 v[4];
        #pragma unroll
        for (int r = 0; r < 4; r++) {
            int i = r * 32 + lane;
            v[r] = (i < n) ? d_selKey[(size_t)bc * SEL_CAP + i] : 0ull;
        }
        #pragma unroll
        for (int k = 2; k <= 128; k <<= 1) {
            #pragma unroll
            for (int j2 = 64; j2 >= 1; j2 >>= 1) {
                if (j2 > (k >> 1)) continue;
                if (j2 >= 32) {
                    int rstep = j2 >> 5;
                    #pragma unroll
                    for (int r = 0; r < 4; r++) {
                        if ((r & rstep) == 0) {
                            int i = r * 32 + lane;
                            bool dird = ((i & k) == 0);
                            u64 lo2 = v[r], hi2 = v[r + rstep];
                            bool sw = dird ? (lo2 < hi2) : (lo2 > hi2);
                            if (sw) { v[r] = hi2; v[r + rstep] = lo2; }
                        }
                    }
                } else {
                    #pragma unroll
                    for (int r = 0; r < 4; r++) {
                        int i = r * 32 + lane;
                        bool dird = ((i & k) == 0);
                        v[r] = ce_shfl(v[r], j2, dird, lane);
                    }
                }
            }
        }
        #pragma unroll
        for (int r = 0; r < 4; r++) s_key[r * 32 + lane] = v[r];
    }
    __syncthreads();

    u64 v = s_key[t];
    u32 key32 = (u32)(v >> 14);
    int anchor = (int)(0x3FFFu - (u32)(v & 0x3FFF));
    float off = __fmul_rn((float)(c + 1), IMGSZ + 1.0f);
    if (t < n) {
        float4 raw = d_dboxes[(size_t)b * NA + anchor];
        float4 bx;
        bx.x = __fadd_rn(raw.x, off);
        bx.y = __fadd_rn(raw.y, off);
        bx.z = __fadd_rn(raw.z, off);
        bx.w = __fadd_rn(raw.w, off);
        s_bx[t] = bx;
        s_ar[t] = __fmul_rn(__fsub_rn(bx.z, bx.x), __fsub_rn(bx.w, bx.y));
        atomicOr(&s_alive[t >> 6], 1ull << (t & 63));
    }
    __syncthreads();

    // warp-cooperative suppression masks: warp wid handles rows i = wid+4k;
    // 32 lanes cover j in parallel, ballot packs kill bits.
    for (int i = wid; i < n; i += 4) {
        float4 bi = s_bx[i];
        float ai = s_ar[i];
        u64 m0 = 0ull, m1 = 0ull;
        for (int jb = i + 1; jb < n; jb += 32) {
            int j = jb + lane;
            bool kill = false;
            if (j < n) {
                float4 bj = s_bx[j];
                float lx = fmaxf(bi.x, bj.x), ly = fmaxf(bi.y, bj.y);
                float rx = fminf(bi.z, bj.z), ry = fminf(bi.w, bj.w);
                float iw = fmaxf(__fsub_rn(rx, lx), 0.f);
                float ih = fmaxf(__fsub_rn(ry, ly), 0.f);
                float inter = __fmul_rn(iw, ih);
                if (inter > 0.f) {
                    float den = __fadd_rn(__fsub_rn(__fadd_rn(ai, s_ar[j]), inter), 1e-9f);
                    kill = (__fdiv_rn(inter, den) > NMS_T);
                }
            }
            u32 bal = __ballot_sync(0xffffffffu, kill);
            if (jb < 64) {
                m0 |= ((u64)bal) << jb;
                if (jb > 32) m1 |= ((u64)bal) >> (64 - jb);
            } else {
                m1 |= ((u64)bal) << (jb - 64);
            }
        }
        if (lane == 0) {
            s_m0[i] = m0; s_m1[i] = m1;
            if (m0 | m1) atomicOr(&s_hk[i >> 6], 1ull << (i & 63));
        }
    }
    __syncthreads();

    if (t == 0) {
        u64 a0 = s_alive[0], a1 = s_alive[1];
        #pragma unroll
        for (int w = 0; w < 2; w++) {
            u64 rem = s_hk[w];
            while (rem) {
                int bit = __ffsll((long long)rem) - 1;
                rem &= rem - 1;
                u64 ab = (w == 0) ? a0 : a1;
                if ((ab >> bit) & 1ull) {
                    int i = (w << 6) + bit;
                    a0 &= ~s_m0[i]; a1 &= ~s_m1[i];
                }
            }
        }
        s_alive[0] = a0; s_alive[1] = a1;
    }
    __syncthreads();

    if (t < n) {
        bool al = (s_alive[t >> 6] >> (t & 63)) & 1ull;
        if (al) {
            u64 fk = ((u64)key32 << 21) | ((u64)(0x7Fu - (u32)c) << 14)
                   | (u64)(0x3FFFu - (u32)anchor);
            int p = atomicAdd(&d_finN[b], 1);
            d_fin[(size_t)b * 9216 + p] = fk;
        }
    }
}

// ===== Kernel 4: per-image final top-200 (score desc, cls asc, anchor asc) =====
__global__ void __launch_bounds__(1024) k_out_fast(float* __restrict__ out) {
    extern __shared__ u64 s_f[];          // 9216 u64 = 72 KB
    __shared__ u64 buf[512];
    __shared__ int s_cnt, s_n, s_okflag;
    int b = blockIdx.x, t = threadIdx.x;
    int n = d_finN[b];

    #pragma unroll
    for (int k = 0; k < 9; k++) {
        int i = t + (k << 10);
        s_f[i] = (i < n) ? d_fin[(size_t)b * 9216 + i] : 0ull;
    }
    if (t < 512) buf[t] = 0ull;
    __syncthreads();

    u32 tau = TAU_MIN;
    int ovf = d_overflow[b];
    if (n > 448) {
        u64 lo = (u64)TAU_MIN + 1, hi = 0xBF800000ull;
        int cntb = n;
        while (lo <= hi) {
            u32 mid = (u32)(lo + ((hi - lo) >> 1));
            if (t == 0) s_cnt = 0;
            __syncthreads();
            int cl = 0;
            #pragma unroll
            for (int k = 0; k < 9; k++)
                cl += ((u32)(s_f[t + (k << 10)] >> 21) >= mid);
            #pragma unroll
            for (int o = 16; o; o >>= 1) cl += __shfl_down_sync(0xffffffffu, cl, o);
            if ((t & 31) == 0) atomicAdd(&s_cnt, cl);
            __syncthreads();
            int cn = s_cnt;
            __syncthreads();
            if (cn >= MAXDET) {
                tau = mid; cntb = cn; lo = (u64)mid + 1;
                if (cn <= 448) break;
            } else hi = (u64)mid - 1;
        }
        if (cntb > 448) ovf = 1;
    }

    if (t == 0) s_n = 0;
    __syncthreads();
    #pragma unroll
    for (int k = 0; k < 9; k++) {
        u64 v = s_f[t + (k << 10)];
        if (v != 0ull && (u32)(v >> 21) >= tau) {
            int p = atomicAdd(&s_n, 1);
            if (p < 512) buf[p] = v;
        }
    }
    __syncthreads();

    for (int k = 2; k <= 512; k <<= 1) {
        for (int j2 = k >> 1; j2 > 0; j2 >>= 1) {
            if (t < 512) {
                int ixj = t ^ j2;
                if (ixj > t) {
                    u64 x = buf[t], y = buf[ixj];
                    bool sw = ((t & k) == 0) ? (x < y) : (x > y);
                    if (sw) { buf[t] = y; buf[ixj] = x; }
                }
            }
            __syncthreads();
        }
    }

    if (t == 0) {
        u64 v199 = buf[MAXDET - 1];
        u32 s200 = (u32)(v199 >> 21);
        u32 cm = d_capmax[b];
        int ok = (!ovf) && (cm == 0u || s200 > cm);
        s_okflag = ok;
        d_ok[b] = ok;
    }
    __syncthreads();

    if (s_okflag && t < MAXDET) {
        u64 v = buf[t];
        float4 bx = make_float4(0.f, 0.f, 0.f, 0.f);
        float so = 0.f, lb = 0.f;
        if (v != 0ull) {
            u32 key32 = (u32)(v >> 21);
            int cls = (int)(0x7Fu - ((u32)(v >> 14) & 0x7Fu));
            int anchor = (int)(0x3FFFu - (u32)(v & 0x3FFF));
            so = __uint_as_float(key32 ^ 0x80000000u);
            bx = d_dboxes[(size_t)b * NA + anchor];
            lb = (float)(cls + 1);
        }
        size_t ob = ((size_t)b * MAXDET + t) * 4;
        out[ob + 0] = bx.x; out[ob + 1] = bx.y;
        out[ob + 2] = bx.z; out[ob + 3] = bx.w;
        out[(size_t)BATCH * MAXDET * 4 + (size_t)b * MAXDET + t] = so;
        out[(size_t)BATCH * MAXDET * 5 + (size_t)b * MAXDET + t] = lb;
    }
}

// ================= FALLBACK (round-8 proven path, gated on !d_ok[b]) =======
#define TKTHREADS 512
#define TKCAP 512

__global__ void __launch_bounds__(TKTHREADS) k_topk_fb() {
    int b = blockIdx.x / NC, c = blockIdx.x % NC;
    if (d_ok[b]) return;
    const float* sc = &d_probs[((size_t)b * NC + c) * NA];
    int t = threadIdx.x;

    u32 key[NLOC];
    #pragma unroll
    for (int j = 0; j < NLOC; j++) {
        int idx = j * TKTHREADS + t;
        float v = (idx < NA) ? sc[idx] : -1.0f;
        key[j] = (idx < NA && v > SCORE_T) ? fmono(v) : 0u;
    }

    __shared__ int s_cnt;
    u64 lo = 0xBC23D70Bull, hi = 0xBF800000ull;
    u32 tau = 0;
    while (lo <= hi) {
        u32 mid = (u32)(lo + ((hi - lo) >> 1));
        if (t == 0) s_cnt = 0;
        __syncthreads();
        int cl = 0;
        #pragma unroll
        for (int j = 0; j < NLOC; j++) cl += (key[j] >= mid);
        #pragma unroll
        for (int o = 16; o; o >>= 1) cl += __shfl_down_sync(0xffffffffu, cl, o);
        if ((t & 31) == 0) atomicAdd(&s_cnt, cl);
        __syncthreads();
        int cnt = s_cnt;
        __syncthreads();
        if (cnt >= KTOP) { tau = mid; lo = (u64)mid + 1; }
        else             { hi = (u64)mid - 1; }
    }

    __shared__ u64 buf[TKCAP];
    __shared__ int s_n;
    if (t == 0) s_n = 0;
    if (t < TKCAP) buf[t] = 0ull;
    __syncthreads();
    #pragma unroll
    for (int j = 0; j < NLOC; j++) {
        if (key[j] != 0u && key[j] >= tau) {
            int p = atomicAdd(&s_n, 1);
            if (p < TKCAP) {
                u32 anchor = (u32)(j * TKTHREADS + t);
                buf[p] = ((u64)key[j] << 32) | (u64)(0xFFFFFFFFu - anchor);
            }
        }
    }
    __syncthreads();

    for (int k = 2; k <= TKCAP; k <<= 1) {
        for (int j2 = k >> 1; j2 > 0; j2 >>= 1) {
            if (t < TKCAP) {
                int ixj = t ^ j2;
                if (ixj > t) {
                    u64 x = buf[t], y = buf[ixj];
                    bool sw = ((t & k) == 0) ? (x < y) : (x > y);
                    if (sw) { buf[t] = y; buf[ixj] = x; }
                }
            }
            __syncthreads();
        }
    }

    int nv = min(s_n, TKCAP);
    size_t obase = (size_t)b * NCAND + (size_t)c * KTOP;
    float off = __fmul_rn((float)(c + 1), IMGSZ + 1.0f);
    if (t < KTOP) {
        float scv = NEG_INF;
        int anc = 0;
        if (t < nv) {
            u64 v = buf[t];
            u32 h32 = (u32)(v >> 32);
            scv = __uint_as_float(h32 ^ 0x80000000u);
            anc = (int)(0xFFFFFFFFu - (u32)v);
        }
        d_candScore[obase + t]  = scv;
        d_candAnchor[obase + t] = anc;
        float4 raw = d_dboxes[(size_t)b * NA + anc];
        float4 ob;
        ob.x = __fadd_rn(raw.x, off);
        ob.y = __fadd_rn(raw.y, off);
        ob.z = __fadd_rn(raw.z, off);
        ob.w = __fadd_rn(raw.w, off);
        d_candBox[obase + t] = ob;
    }
}

__global__ void __launch_bounds__(416) k_nms_fb() {
    int b = blockIdx.x / NC, c = blockIdx.x % NC;
    if (d_ok[b]) return;
    __shared__ float  s_sc[KTOP];
    __shared__ float4 s_bx[KTOP];
    __shared__ float  s_ar[KTOP];
    __shared__ int    s_alive[KTOP];
    int t = threadIdx.x;
    size_t base = (size_t)b * NCAND + (size_t)c * KTOP;

    float4 my = make_float4(0.f, 0.f, 0.f, 0.f);
    float mya = 0.f;
    if (t < KTOP) {
        float s = d_candScore[base + t];
        float4 bx = d_candBox[base + t];
        s_sc[t] = s;
        s_bx[t] = bx;
        float ar = __fmul_rn(__fsub_rn(bx.z, bx.x), __fsub_rn(bx.w, bx.y));
        s_ar[t] = ar;
        s_alive[t] = isfinite(s) ? 1 : 0;
        my = bx; mya = ar;
    }
    __syncthreads();

    for (int i = 0; i < KTOP; i++) {
        if (s_alive[i]) {
            if (t > i && t < KTOP && s_alive[t]) {
                float4 bi = s_bx[i];
                float lx = fmaxf(bi.x, my.x), ly = fmaxf(bi.y, my.y);
                float rx = fminf(bi.z, my.z), ry = fminf(bi.w, my.w);
                float iw = fmaxf(__fsub_rn(rx, lx), 0.f);
                float ih = fmaxf(__fsub_rn(ry, ly), 0.f);
                float inter = __fmul_rn(iw, ih);
                float den = __fadd_rn(__fsub_rn(__fadd_rn(s_ar[i], mya), inter), 1e-9f);
                float iou = __fdiv_rn(inter, den);
                if (iou > NMS_T) s_alive[t] = 0;
            }
            __syncthreads();
        }
    }
    __syncthreads();
    if (t < KTOP)
        d_candScore[base + t] = s_alive[t] ? s_sc[t] : NEG_INF;
}

#define SELPAD 36864
__global__ void __launch_bounds__(1024) k_select_fb(float* __restrict__ out) {
    int b = blockIdx.x, t = threadIdx.x;
    if (d_ok[b]) return;
    extern __shared__ u32 s_key2[];
    __shared__ u64 buf[512];
    __shared__ int s_cnt, s_n;

    for (int i = t; i < NCAND; i += 1024) {
        float v = d_candScore[(size_t)b * NCAND + i];
        s_key2[i] = isfinite(v) ? fmono(v) : 0u;
    }
    for (int i = NCAND + t; i < SELPAD; i += 1024) s_key2[i] = 0u;
    if (t < 512) buf[t] = 0ull;

    u64 lo = 0xBC23D70Bull, hi = 0xBF800000ull;
    u32 tau = 0;
    const uint4* k4 = (const uint4*)s_key2;
    __syncthreads();
    while (lo <= hi) {
        u32 mid = (u32)(lo + ((hi - lo) >> 1));
        if (t == 0) s_cnt = 0;
        __syncthreads();
        int cl = 0;
        #pragma unroll
        for (int k = 0; k < 9; k++) {
            uint4 v = k4[t + (k << 10)];
            cl += (v.x >= mid) + (v.y >= mid) + (v.z >= mid) + (v.w >= mid);
        }
        #pragma unroll
        for (int o = 16; o; o >>= 1) cl += __shfl_down_sync(0xffffffffu, cl, o);
        if ((t & 31) == 0) atomicAdd(&s_cnt, cl);
        __syncthreads();
        int cnt = s_cnt;
        __syncthreads();
        if (cnt >= MAXDET) { tau = mid; lo = (u64)mid + 1; }
        else               { hi = (u64)mid - 1; }
    }
    if (t == 0) s_n = 0;
    __syncthreads();
    #pragma unroll
    for (int k = 0; k < 36; k++) {
        int i = t + (k << 10);
        if (i < NCAND) {
            u32 kv = s_key2[i];
            if (kv >= tau) {
                int p = atomicAdd(&s_n, 1);
                if (p < 512)
                    buf[p] = ((u64)kv << 32) | (u64)(0xFFFFFFFFu - (u32)i);
            }
        }
    }
    __syncthreads();

    for (int k = 2; k <= 512; k <<= 1) {
        for (int j2 = k >> 1; j2 > 0; j2 >>= 1) {
            if (t < 512) {
                int ixj = t ^ j2;
                if (ixj > t) {
                    u64 x = buf[t], y = buf[ixj];
                    bool sw = ((t & k) == 0) ? (x < y) : (x > y);
                    if (sw) { buf[t] = y; buf[ixj] = x; }
                }
            }
            __syncthreads();
        }
    }

    if (t < MAXDET) {
        u64 v = buf[t];
        u32 h = (u32)(v >> 32);
        float4 bx = make_float4(0.f, 0.f, 0.f, 0.f);
        float so = 0.f, lb = 0.f;
        if (h != 0u) {
            int idx = (int)(0xFFFFFFFFu - (u32)v);
            so = __uint_as_float(h ^ 0x80000000u);
            int cls = idx / KTOP;
            int anc = d_candAnchor[(size_t)b * NCAND + idx];
            bx = d_dboxes[(size_t)b * NA + anc];
            lb = (float)(cls + 1);
        }
        size_t ob = ((size_t)b * MAXDET + t) * 4;
        out[ob + 0] = bx.x; out[ob + 1] = bx.y;
        out[ob + 2] = bx.z; out[ob + 3] = bx.w;
        out[(size_t)BATCH * MAXDET * 4 + (size_t)b * MAXDET + t] = so;
        out[(size_t)BATCH * MAXDET * 5 + (size_t)b * MAXDET + t] = lb;
    }
}

// ================= host =================
extern "C" void kernel_launch(void* const* d_in, const int* in_sizes, int n_in,
                              void* d_out, int out_size) {
    const float* logits  = (const float*)d_in[0];
    const float* reg     = (const float*)d_in[1];
    const float* anchors = (const float*)d_in[2];
    float* out = (float*)d_out;

    k_softmax_decode<<<(BATCH * NA) / 32, 1024>>>(logits, reg, anchors);
    k_selclass<<<BATCH * NC, 512>>>();
    k_nms_fast<<<BATCH * NC, 128>>>();
    cudaFuncSetAttribute(k_out_fast, cudaFuncAttributeMaxDynamicSharedMemorySize,
                         9216 * (int)sizeof(u64));
    k_out_fast<<<BATCH, 1024, 9216 * sizeof(u64)>>>(out);
    // fallback chain (no-ops when fast path verified exact)
    k_topk_fb<<<BATCH * NC, TKTHREADS>>>();
    k_nms_fb<<<BATCH * NC, 416>>>();
    cudaFuncSetAttribute(k_select_fb, cudaFuncAttributeMaxDynamicSharedMemorySize,
                         SELPAD * (int)sizeof(u32));
    k_select_fb<<<BATCH, 1024, SELPAD * sizeof(u32)>>>(out);
}

// round 13
// speedup vs baseline: 1.0900x; 1.0900x over previous
#include <cuda_runtime.h>

#define BATCH   32
#define NA      8732
#define NCLASS  91
#define NC      90
#define KTOP    400
#define NCAND   (NC * KTOP)      /* 36000 */
#define MAXDET  200
#define IMGSZ   300.0f
#define SCORE_T 0.01f
#define NMS_T   0.45f
#define BBOX_CLIP 4.135166556742356f
#define NEG_INF __int_as_float(0xff800000)
#define TAU_MIN 0xBC23D70Cu      /* fmono(0.01f)+1 : smallest passing key */

typedef unsigned long long u64;
typedef unsigned u32;

// -------- scratch (device globals; no allocations allowed) --------
__device__ float  d_probs[(size_t)BATCH * NC * NA];
__device__ float4 d_dboxes[(size_t)BATCH * NA];
// fast path
#define SEL_CAP 96
__device__ u64 d_selKey[(size_t)BATCH * NC * SEL_CAP];
__device__ int d_selN[BATCH * NC];
__device__ u32 d_capmax[BATCH];
__device__ int d_overflow[BATCH];
__device__ u64 d_fin[(size_t)BATCH * 9216];
__device__ int d_finN[BATCH];
__device__ int d_ok[BATCH];
// fallback path
__device__ float  d_candScore[(size_t)BATCH * NCAND];
__device__ int    d_candAnchor[(size_t)BATCH * NCAND];
__device__ float4 d_candBox[(size_t)BATCH * NCAND];

__device__ __forceinline__ u32 fmono(float f) {
    u32 u = __float_as_uint(f);
    return u ^ ((u >> 31) ? 0xFFFFFFFFu : 0x80000000u);
}

// ================= Kernel 1: softmax (XLA:GPU warp row-reduce order) + decode
// FROZEN FP ARITHMETIC for every value that can reach the output.
// Division gating: thr = RN(s*0.00999); e <= thr provably implies
// RN(e/s) < 0.01f, so those lanes skip the fdiv entirely (no MUFU added).
__global__ void __launch_bounds__(1024) k_softmax_decode(
        const float* __restrict__ logits,
        const float* __restrict__ reg,
        const float* __restrict__ anchors) {
    __shared__ float s_p[NC][33];
    int w = threadIdx.x >> 5, lane = threadIdx.x & 31;
    long flat = (long)blockIdx.x * 32 + w;
    size_t lbase = (size_t)flat * NCLASS;
    int b0 = (int)((blockIdx.x * 32) / NA);
    int a0 = (int)(blockIdx.x * 32 - b0 * NA);

    if (blockIdx.x == 0 && threadIdx.x < BATCH) {     // folded init
        d_capmax[threadIdx.x] = 0u; d_overflow[threadIdx.x] = 0;
        d_finN[threadIdx.x] = 0;    d_ok[threadIdx.x] = 0;
    }

    float x0 = logits[lbase + lane];
    float x1 = logits[lbase + lane + 32];
    float x2 = (lane < 27) ? logits[lbase + lane + 64] : NEG_INF;

    float m = fmaxf(fmaxf(x0, x1), x2);
    #pragma unroll
    for (int o = 16; o; o >>= 1) m = fmaxf(m, __shfl_down_sync(0xffffffffu, m, o));
    m = __shfl_sync(0xffffffffu, m, 0);

    float e0 = expf(x0 - m), e1 = expf(x1 - m), e2 = expf(x2 - m);
    float s = __fadd_rn(__fadd_rn(e0, e1), e2);
    #pragma unroll
    for (int o = 16; o; o >>= 1) s = __fadd_rn(s, __shfl_down_sync(0xffffffffu, s, o));
    s = __shfl_sync(0xffffffffu, s, 0);

    float thr = __fmul_rn(s, 0.00999f);   // warp-uniform provable-mask cutoff
    if (lane >= 1) {
        float p = (e0 > thr) ? __fdiv_rn(e0, s) : NEG_INF;
        s_p[lane - 1][w] = (p > SCORE_T) ? p : NEG_INF;
    }
    {
        float p = (e1 > thr) ? __fdiv_rn(e1, s) : NEG_INF;
        s_p[lane + 31][w] = (p > SCORE_T) ? p : NEG_INF;
    }
    if (lane < 27) {
        float p = (e2 > thr) ? __fdiv_rn(e2, s) : NEG_INF;
        s_p[lane + 63][w] = (p > SCORE_T) ? p : NEG_INF;
    }
    __syncthreads();

    #pragma unroll
    for (int i = threadIdx.x; i < NC * 32; i += 1024) {
        int c = i >> 5, wl = i & 31;
        int a = a0 + wl, b = b0;
        if (a >= NA) { a -= NA; b++; }
        d_probs[((size_t)b * NC + c) * NA + a] = s_p[c][wl];
    }

    if (threadIdx.x < 32) {
        int a = a0 + threadIdx.x, b = b0;
        if (a >= NA) { a -= NA; b++; }
        long fl = (long)blockIdx.x * 32 + threadIdx.x;
        float4 rg = ((const float4*)reg)[fl];
        float4 an = ((const float4*)anchors)[a];
        float wa = __fsub_rn(an.z, an.x), ha = __fsub_rn(an.w, an.y);
        float cxa = __fadd_rn(an.x, __fmul_rn(0.5f, wa));
        float cya = __fadd_rn(an.y, __fmul_rn(0.5f, ha));
        float dx = __fdiv_rn(rg.x, 10.0f), dy = __fdiv_rn(rg.y, 10.0f);
        float dw = fminf(__fdiv_rn(rg.z, 5.0f), BBOX_CLIP);
        float dh = fminf(__fdiv_rn(rg.w, 5.0f), BBOX_CLIP);
        float cx = __fadd_rn(__fmul_rn(dx, wa), cxa);
        float cy = __fadd_rn(__fmul_rn(dy, ha), cya);
        float bw = __fmul_rn(expf(dw), wa), bh = __fmul_rn(expf(dh), ha);
        float hw = __fmul_rn(0.5f, bw), hh = __fmul_rn(0.5f, bh);
        float4 bx;
        bx.x = fminf(fmaxf(__fsub_rn(cx, hw), 0.f), IMGSZ);
        bx.y = fminf(fmaxf(__fsub_rn(cy, hh), 0.f), IMGSZ);
        bx.z = fminf(fmaxf(__fadd_rn(cx, hw), 0.f), IMGSZ);
        bx.w = fminf(fmaxf(__fadd_rn(cy, hh), 0.f), IMGSZ);
        d_dboxes[(size_t)b * NA + a] = bx;
    }
}

// ===== Kernel 2: per-(b,c) select all candidates >= tau_c (64..96 pass) =====
#define NLOC 18

__global__ void __launch_bounds__(512) k_selclass() {
    int bc = blockIdx.x;
    int b = bc / NC;
    const float* sc = &d_probs[(size_t)bc * NA];
    int t = threadIdx.x;

    u32 key[NLOC];
    #pragma unroll
    for (int j = 0; j < NLOC; j++) {
        int idx = j * 512 + t;
        float v = (idx < NA) ? sc[idx] : -1.0f;
        key[j] = (idx < NA && v > SCORE_T) ? fmono(v) : 0u;
    }

    __shared__ int s_cnt;
    __shared__ int s_n;

    if (t == 0) s_cnt = 0;
    __syncthreads();
    {
        int cl = 0;
        #pragma unroll
        for (int j = 0; j < NLOC; j++) cl += (key[j] >= TAU_MIN);
        #pragma unroll
        for (int o = 16; o; o >>= 1) cl += __shfl_down_sync(0xffffffffu, cl, o);
        if ((t & 31) == 0) atomicAdd(&s_cnt, cl);
    }
    __syncthreads();
    int cnt0 = s_cnt;
    __syncthreads();

    u32 tau = TAU_MIN;
    int capped = 0;
    if (cnt0 > SEL_CAP) {
        capped = 1;
        u64 lo = (u64)TAU_MIN + 1, hi = 0xBF800000ull;
        while (lo <= hi) {
            u32 mid = (u32)(lo + ((hi - lo) >> 1));
            if (t == 0) s_cnt = 0;
            __syncthreads();
            int cl = 0;
            #pragma unroll
            for (int j = 0; j < NLOC; j++) cl += (key[j] >= mid);
            #pragma unroll
            for (int o = 16; o; o >>= 1) cl += __shfl_down_sync(0xffffffffu, cl, o);
            if ((t & 31) == 0) atomicAdd(&s_cnt, cl);
            __syncthreads();
            int cn = s_cnt;
            __syncthreads();
            if (cn >= 64) {
                tau = mid; lo = (u64)mid + 1;
                if (cn <= SEL_CAP) break;
            } else hi = (u64)mid - 1;
        }
    }

    if (t == 0) s_n = 0;
    __syncthreads();
    #pragma unroll
    for (int j = 0; j < NLOC; j++) {
        if (key[j] >= tau) {
            int p = atomicAdd(&s_n, 1);
            if (p < SEL_CAP) {
                u32 anchor = (u32)(j * 512 + t);
                d_selKey[(size_t)bc * SEL_CAP + p] =
                    ((u64)key[j] << 14) | (u64)(0x3FFFu - anchor);
            }
        }
    }
    __syncthreads();
    if (t == 0) {
        int n = s_n;
        d_selN[bc] = (n < SEL_CAP) ? n : SEL_CAP;
        if (n > SEL_CAP) d_overflow[b] = 1;
        if (capped) atomicMax(&d_capmax[b], tau);
    }
}

// ---- warp-register bitonic helpers (128 u64, 4/lane, descending) ----
__device__ __forceinline__ u64 ce_shfl(u64 x, int j2, bool dird, int lane) {
    u64 y = __shfl_xor_sync(0xffffffffu, x, j2);
    bool lower = (lane & j2) == 0;
    bool keepmax = (dird == lower);
    u64 mx = (x > y) ? x : y;
    u64 mn = (x > y) ? y : x;
    return keepmax ? mx : mn;
}

// ===== Kernel 3: per-(b,c) warp-sort<=128 + greedy NMS + emit survivors =====
__global__ void __launch_bounds__(128) k_nms_fast() {
    int bc = blockIdx.x;
    int b = bc / NC, c = bc % NC;
    int n = d_selN[bc];
    if (n == 0) return;
    int t = threadIdx.x;

    __shared__ u64   s_key[128];
    __shared__ float4 s_bx[SEL_CAP];
    __shared__ float  s_ar[SEL_CAP];
    __shared__ u64   s_m0[SEL_CAP], s_m1[SEL_CAP];
    __shared__ u64   s_alive[2], s_hk[2];

    if (t < 2) { s_alive[t] = 0ull; s_hk[t] = 0ull; }

    if (t < 32) {
        int lane = t;
        u64 v[4];
        #pragma unroll
        for (int r = 0; r < 4; r++) {
            int i = r * 32 + lane;
            v[r] = (i < n) ? d_selKey[(size_t)bc * SEL_CAP + i] : 0ull;
        }
        #pragma unroll
        for (int k = 2; k <= 128; k <<= 1) {
            #pragma unroll
            for (int j2 = 64; j2 >= 1; j2 >>= 1) {
                if (j2 > (k >> 1)) continue;
                if (j2 >= 32) {
                    int rstep = j2 >> 5;
                    #pragma unroll
                    for (int r = 0; r < 4; r++) {
                        if ((r & rstep) == 0) {
                            int i = r * 32 + lane;
                            bool dird = ((i & k) == 0);
                            u64 lo2 = v[r], hi2 = v[r + rstep];
                            bool sw = dird ? (lo2 < hi2) : (lo2 > hi2);
                            if (sw) { v[r] = hi2; v[r + rstep] = lo2; }
                        }
                    }
                } else {
                    #pragma unroll
                    for (int r = 0; r < 4; r++) {
                        int i = r * 32 + lane;
                        bool dird = ((i & k) == 0);
                        v[r] = ce_shfl(v[r], j2, dird, lane);
                    }
                }
            }
        }
        #pragma unroll
        for (int r = 0; r < 4; r++) s_key[r * 32 + lane] = v[r];
    }
    __syncthreads();

    u64 v = s_key[t];
    u32 key32 = (u32)(v >> 14);
    int anchor = (int)(0x3FFFu - (u32)(v & 0x3FFF));
    float off = __fmul_rn((float)(c + 1), IMGSZ + 1.0f);
    if (t < n) {
        float4 raw = d_dboxes[(size_t)b * NA + anchor];
        float4 bx;
        bx.x = __fadd_rn(raw.x, off);
        bx.y = __fadd_rn(raw.y, off);
        bx.z = __fadd_rn(raw.z, off);
        bx.w = __fadd_rn(raw.w, off);
        s_bx[t] = bx;
        s_ar[t] = __fmul_rn(__fsub_rn(bx.z, bx.x), __fsub_rn(bx.w, bx.y));
        atomicOr(&s_alive[t >> 6], 1ull << (t & 63));
    }
    __syncthreads();

    if (t < n) {
        float4 bi = s_bx[t];
        float ai = s_ar[t];
        u64 m0 = 0ull, m1 = 0ull;
        for (int j = t + 1; j < n; j++) {
            float4 bj = s_bx[j];
            float lx = fmaxf(bi.x, bj.x), ly = fmaxf(bi.y, bj.y);
            float rx = fminf(bi.z, bj.z), ry = fminf(bi.w, bj.w);
            float iw = fmaxf(__fsub_rn(rx, lx), 0.f);
            float ih = fmaxf(__fsub_rn(ry, ly), 0.f);
            float inter = __fmul_rn(iw, ih);
            bool kill = false;
            if (inter > 0.f) {
                float den = __fadd_rn(__fsub_rn(__fadd_rn(ai, s_ar[j]), inter), 1e-9f);
                kill = (__fdiv_rn(inter, den) > NMS_T);
            }
            if (j < 64) m0 |= ((u64)kill) << j;
            else        m1 |= ((u64)kill) << (j - 64);
        }
        s_m0[t] = m0; s_m1[t] = m1;
        if (m0 | m1) atomicOr(&s_hk[t >> 6], 1ull << (t & 63));
    }
    __syncthreads();

    if (t == 0) {
        u64 a0 = s_alive[0], a1 = s_alive[1];
        #pragma unroll
        for (int w = 0; w < 2; w++) {
            u64 rem = s_hk[w];
            while (rem) {
                int bit = __ffsll((long long)rem) - 1;
                rem &= rem - 1;
                u64 ab = (w == 0) ? a0 : a1;
                if ((ab >> bit) & 1ull) {
                    int i = (w << 6) + bit;
                    a0 &= ~s_m0[i]; a1 &= ~s_m1[i];
                }
            }
        }
        s_alive[0] = a0; s_alive[1] = a1;
    }
    __syncthreads();

    if (t < n) {
        bool al = (s_alive[t >> 6] >> (t & 63)) & 1ull;
        if (al) {
            u64 fk = ((u64)key32 << 21) | ((u64)(0x7Fu - (u32)c) << 14)
                   | (u64)(0x3FFFu - (u32)anchor);
            int p = atomicAdd(&d_finN[b], 1);
            d_fin[(size_t)b * 9216 + p] = fk;
        }
    }
}

// ===== Kernel 4: per-image final top-200 (score desc, cls asc, anchor asc) =====
__global__ void __launch_bounds__(1024) k_out_fast(float* __restrict__ out) {
    extern __shared__ u64 s_f[];          // 9216 u64 = 72 KB
    __shared__ u64 buf[512];
    __shared__ int s_cnt, s_n, s_okflag;
    int b = blockIdx.x, t = threadIdx.x;
    int n = d_finN[b];

    #pragma unroll
    for (int k = 0; k < 9; k++) {
        int i = t + (k << 10);
        s_f[i] = (i < n) ? d_fin[(size_t)b * 9216 + i] : 0ull;
    }
    if (t < 512) buf[t] = 0ull;
    __syncthreads();

    u32 tau = TAU_MIN;
    int ovf = d_overflow[b];
    if (n > 448) {
        u64 lo = (u64)TAU_MIN + 1, hi = 0xBF800000ull;
        int cntb = n;
        while (lo <= hi) {
            u32 mid = (u32)(lo + ((hi - lo) >> 1));
            if (t == 0) s_cnt = 0;
            __syncthreads();
            int cl = 0;
            #pragma unroll
            for (int k = 0; k < 9; k++)
                cl += ((u32)(s_f[t + (k << 10)] >> 21) >= mid);
            #pragma unroll
            for (int o = 16; o; o >>= 1) cl += __shfl_down_sync(0xffffffffu, cl, o);
            if ((t & 31) == 0) atomicAdd(&s_cnt, cl);
            __syncthreads();
            int cn = s_cnt;
            __syncthreads();
            if (cn >= MAXDET) {
                tau = mid; cntb = cn; lo = (u64)mid + 1;
                if (cn <= 448) break;
            } else hi = (u64)mid - 1;
        }
        if (cntb > 448) ovf = 1;
    }

    if (t == 0) s_n = 0;
    __syncthreads();
    #pragma unroll
    for (int k = 0; k < 9; k++) {
        u64 v = s_f[t + (k << 10)];
        if (v != 0ull && (u32)(v >> 21) >= tau) {
            int p = atomicAdd(&s_n, 1);
            if (p < 512) buf[p] = v;
        }
    }
    __syncthreads();

    for (int k = 2; k <= 512; k <<= 1) {
        for (int j2 = k >> 1; j2 > 0; j2 >>= 1) {
            if (t < 512) {
                int ixj = t ^ j2;
                if (ixj > t) {
                    u64 x = buf[t], y = buf[ixj];
                    bool sw = ((t & k) == 0) ? (x < y) : (x > y);
                    if (sw) { buf[t] = y; buf[ixj] = x; }
                }
            }
            __syncthreads();
        }
    }

    if (t == 0) {
        u64 v199 = buf[MAXDET - 1];
        u32 s200 = (u32)(v199 >> 21);
        u32 cm = d_capmax[b];
        int ok = (!ovf) && (cm == 0u || s200 > cm);
        s_okflag = ok;
        d_ok[b] = ok;
    }
    __syncthreads();

    if (s_okflag && t < MAXDET) {
        u64 v = buf[t];
        float4 bx = make_float4(0.f, 0.f, 0.f, 0.f);
        float so = 0.f, lb = 0.f;
        if (v != 0ull) {
            u32 key32 = (u32)(v >> 21);
            int cls = (int)(0x7Fu - ((u32)(v >> 14) & 0x7Fu));
            int anchor = (int)(0x3FFFu - (u32)(v & 0x3FFF));
            so = __uint_as_float(key32 ^ 0x80000000u);
            bx = d_dboxes[(size_t)b * NA + anchor];
            lb = (float)(cls + 1);
        }
        size_t ob = ((size_t)b * MAXDET + t) * 4;
        out[ob + 0] = bx.x; out[ob + 1] = bx.y;
        out[ob + 2] = bx.z; out[ob + 3] = bx.w;
        out[(size_t)BATCH * MAXDET * 4 + (size_t)b * MAXDET + t] = so;
        out[(size_t)BATCH * MAXDET * 5 + (size_t)b * MAXDET + t] = lb;
    }
}

// ================= FALLBACK (round-8 proven path, gated on !d_ok[b]) =======
#define TKTHREADS 512
#define TKCAP 512

__global__ void __launch_bounds__(TKTHREADS) k_topk_fb() {
    int b = blockIdx.x / NC, c = blockIdx.x % NC;
    if (d_ok[b]) return;
    const float* sc = &d_probs[((size_t)b * NC + c) * NA];
    int t = threadIdx.x;

    u32 key[NLOC];
    #pragma unroll
    for (int j = 0; j < NLOC; j++) {
        int idx = j * TKTHREADS + t;
        float v = (idx < NA) ? sc[idx] : -1.0f;
        key[j] = (idx < NA && v > SCORE_T) ? fmono(v) : 0u;
    }

    __shared__ int s_cnt;
    u64 lo = 0xBC23D70Bull, hi = 0xBF800000ull;
    u32 tau = 0;
    while (lo <= hi) {
        u32 mid = (u32)(lo + ((hi - lo) >> 1));
        if (t == 0) s_cnt = 0;
        __syncthreads();
        int cl = 0;
        #pragma unroll
        for (int j = 0; j < NLOC; j++) cl += (key[j] >= mid);
        #pragma unroll
        for (int o = 16; o; o >>= 1) cl += __shfl_down_sync(0xffffffffu, cl, o);
        if ((t & 31) == 0) atomicAdd(&s_cnt, cl);
        __syncthreads();
        int cnt = s_cnt;
        __syncthreads();
        if (cnt >= KTOP) { tau = mid; lo = (u64)mid + 1; }
        else             { hi = (u64)mid - 1; }
    }

    __shared__ u64 buf[TKCAP];
    __shared__ int s_n;
    if (t == 0) s_n = 0;
    if (t < TKCAP) buf[t] = 0ull;
    __syncthreads();
    #pragma unroll
    for (int j = 0; j < NLOC; j++) {
        if (key[j] != 0u && key[j] >= tau) {
            int p = atomicAdd(&s_n, 1);
            if (p < TKCAP) {
                u32 anchor = (u32)(j * TKTHREADS + t);
                buf[p] = ((u64)key[j] << 32) | (u64)(0xFFFFFFFFu - anchor);
            }
        }
    }
    __syncthreads();

    for (int k = 2; k <= TKCAP; k <<= 1) {
        for (int j2 = k >> 1; j2 > 0; j2 >>= 1) {
            if (t < TKCAP) {
                int ixj = t ^ j2;
                if (ixj > t) {
                    u64 x = buf[t], y = buf[ixj];
                    bool sw = ((t & k) == 0) ? (x < y) : (x > y);
                    if (sw) { buf[t] = y; buf[ixj] = x; }
                }
            }
            __syncthreads();
        }
    }

    int nv = min(s_n, TKCAP);
    size_t obase = (size_t)b * NCAND + (size_t)c * KTOP;
    float off = __fmul_rn((float)(c + 1), IMGSZ + 1.0f);
    if (t < KTOP) {
        float scv = NEG_INF;
        int anc = 0;
        if (t < nv) {
            u64 v = buf[t];
            u32 h32 = (u32)(v >> 32);
            scv = __uint_as_float(h32 ^ 0x80000000u);
            anc = (int)(0xFFFFFFFFu - (u32)v);
        }
        d_candScore[obase + t]  = scv;
        d_candAnchor[obase + t] = anc;
        float4 raw = d_dboxes[(size_t)b * NA + anc];
        float4 ob;
        ob.x = __fadd_rn(raw.x, off);
        ob.y = __fadd_rn(raw.y, off);
        ob.z = __fadd_rn(raw.z, off);
        ob.w = __fadd_rn(raw.w, off);
        d_candBox[obase + t] = ob;
    }
}

__global__ void __launch_bounds__(416) k_nms_fb() {
    int b = blockIdx.x / NC, c = blockIdx.x % NC;
    if (d_ok[b]) return;
    __shared__ float  s_sc[KTOP];
    __shared__ float4 s_bx[KTOP];
    __shared__ float  s_ar[KTOP];
    __shared__ int    s_alive[KTOP];
    int t = threadIdx.x;
    size_t base = (size_t)b * NCAND + (size_t)c * KTOP;

    float4 my = make_float4(0.f, 0.f, 0.f, 0.f);
    float mya = 0.f;
    if (t < KTOP) {
        float s = d_candScore[base + t];
        float4 bx = d_candBox[base + t];
        s_sc[t] = s;
        s_bx[t] = bx;
        float ar = __fmul_rn(__fsub_rn(bx.z, bx.x), __fsub_rn(bx.w, bx.y));
        s_ar[t] = ar;
        s_alive[t] = isfinite(s) ? 1 : 0;
        my = bx; mya = ar;
    }
    __syncthreads();

    for (int i = 0; i < KTOP; i++) {
        if (s_alive[i]) {
            if (t > i && t < KTOP && s_alive[t]) {
                float4 bi = s_bx[i];
                float lx = fmaxf(bi.x, my.x), ly = fmaxf(bi.y, my.y);
                float rx = fminf(bi.z, my.z), ry = fminf(bi.w, my.w);
                float iw = fmaxf(__fsub_rn(rx, lx), 0.f);
                float ih = fmaxf(__fsub_rn(ry, ly), 0.f);
                float inter = __fmul_rn(iw, ih);
                float den = __fadd_rn(__fsub_rn(__fadd_rn(s_ar[i], mya), inter), 1e-9f);
                float iou = __fdiv_rn(inter, den);
                if (iou > NMS_T) s_alive[t] = 0;
            }
            __syncthreads();
        }
    }
    __syncthreads();
    if (t < KTOP)
        d_candScore[base + t] = s_alive[t] ? s_sc[t] : NEG_INF;
}

#define SELPAD 36864
__global__ void __launch_bounds__(1024) k_select_fb(float* __restrict__ out) {
    int b = blockIdx.x, t = threadIdx.x;
    if (d_ok[b]) return;
    extern __shared__ u32 s_key2[];
    __shared__ u64 buf[512];
    __shared__ int s_cnt, s_n;

    for (int i = t; i < NCAND; i += 1024) {
        float v = d_candScore[(size_t)b * NCAND + i];
        s_key2[i] = isfinite(v) ? fmono(v) : 0u;
    }
    for (int i = NCAND + t; i < SELPAD; i += 1024) s_key2[i] = 0u;
    if (t < 512) buf[t] = 0ull;

    u64 lo = 0xBC23D70Bull, hi = 0xBF800000ull;
    u32 tau = 0;
    const uint4* k4 = (const uint4*)s_key2;
    __syncthreads();
    while (lo <= hi) {
        u32 mid = (u32)(lo + ((hi - lo) >> 1));
        if (t == 0) s_cnt = 0;
        __syncthreads();
        int cl = 0;
        #pragma unroll
        for (int k = 0; k < 9; k++) {
            uint4 v = k4[t + (k << 10)];
            cl += (v.x >= mid) + (v.y >= mid) + (v.z >= mid) + (v.w >= mid);
        }
        #pragma unroll
        for (int o = 16; o; o >>= 1) cl += __shfl_down_sync(0xffffffffu, cl, o);
        if ((t & 31) == 0) atomicAdd(&s_cnt, cl);
        __syncthreads();
        int cnt = s_cnt;
        __syncthreads();
        if (cnt >= MAXDET) { tau = mid; lo = (u64)mid + 1; }
        else               { hi = (u64)mid - 1; }
    }
    if (t == 0) s_n = 0;
    __syncthreads();
    #pragma unroll
    for (int k = 0; k < 36; k++) {
        int i = t + (k << 10);
        if (i < NCAND) {
            u32 kv = s_key2[i];
            if (kv >= tau) {
                int p = atomicAdd(&s_n, 1);
                if (p < 512)
                    buf[p] = ((u64)kv << 32) | (u64)(0xFFFFFFFFu - (u32)i);
            }
        }
    }
    __syncthreads();

    for (int k = 2; k <= 512; k <<= 1) {
        for (int j2 = k >> 1; j2 > 0; j2 >>= 1) {
            if (t < 512) {
                int ixj = t ^ j2;
                if (ixj > t) {
                    u64 x = buf[t], y = buf[ixj];
                    bool sw = ((t & k) == 0) ? (x < y) : (x > y);
                    if (sw) { buf[t] = y; buf[ixj] = x; }
                }
            }
            __syncthreads();
        }
    }

    if (t < MAXDET) {
        u64 v = buf[t];
        u32 h = (u32)(v >> 32);
        float4 bx = make_float4(0.f, 0.f, 0.f, 0.f);
        float so = 0.f, lb = 0.f;
        if (h != 0u) {
            int idx = (int)(0xFFFFFFFFu - (u32)v);
            so = __uint_as_float(h ^ 0x80000000u);
            int cls = idx / KTOP;
            int anc = d_candAnchor[(size_t)b * NCAND + idx];
            bx = d_dboxes[(size_t)b * NA + anc];
            lb = (float)(cls + 1);
        }
        size_t ob = ((size_t)b * MAXDET + t) * 4;
        out[ob + 0] = bx.x; out[ob + 1] = bx.y;
        out[ob + 2] = bx.z; out[ob + 3] = bx.w;
        out[(size_t)BATCH * MAXDET * 4 + (size_t)b * MAXDET + t] = so;
        out[(size_t)BATCH * MAXDET * 5 + (size_t)b * MAXDET + t] = lb;
    }
}

// ================= host =================
extern "C" void kernel_launch(void* const* d_in, const int* in_sizes, int n_in,
                              void* d_out, int out_size) {
    const float* logits  = (const float*)d_in[0];
    const float* reg     = (const float*)d_in[1];
    const float* anchors = (const float*)d_in[2];
    float* out = (float*)d_out;

    k_softmax_decode<<<(BATCH * NA) / 32, 1024>>>(logits, reg, anchors);
    k_selclass<<<BATCH * NC, 512>>>();
    k_nms_fast<<<BATCH * NC, 128>>>();
    cudaFuncSetAttribute(k_out_fast, cudaFuncAttributeMaxDynamicSharedMemorySize,
                         9216 * (int)sizeof(u64));
    k_out_fast<<<BATCH, 1024, 9216 * sizeof(u64)>>>(out);
    // fallback chain (no-ops when fast path verified exact)
    k_topk_fb<<<BATCH * NC, TKTHREADS>>>();
    k_nms_fb<<<BATCH * NC, 416>>>();
    cudaFuncSetAttribute(k_select_fb, cudaFuncAttributeMaxDynamicSharedMemorySize,
                         SELPAD * (int)sizeof(u32));
    k_select_fb<<<BATCH, 1024, SELPAD * sizeof(u32)>>>(out);
}

// round 14
// speedup vs baseline: 1.3771x; 1.2635x over previous
#include <cuda_runtime.h>

#define BATCH   32
#define NA      8732
#define NCLASS  91
#define NC      90
#define KTOP    400
#define NCAND   (NC * KTOP)      /* 36000 */
#define MAXDET  200
#define IMGSZ   300.0f
#define SCORE_T 0.01f
#define NMS_T   0.45f
#define BBOX_CLIP 4.135166556742356f
#define NEG_INF __int_as_float(0xff800000)
#define TAU_MIN 0xBC23D70Cu      /* fmono(0.01f)+1 */
#define T0      0.07f            /* fixed emission threshold (verified safe) */
#define BCAP    128              /* bucket capacity per (b,c) */
#define FINCAP  9216

typedef unsigned long long u64;
typedef unsigned u32;

// -------- scratch (device globals; no allocations allowed) --------
__device__ float  d_probs[(size_t)BATCH * NC * NA];      // fallback only
__device__ float4 d_dboxes[(size_t)BATCH * NA];
// fast path
__device__ u64 d_selKey[(size_t)BATCH * NC * BCAP];
__device__ int d_selN[BATCH * NC];
__device__ u32 d_capmax[BATCH];
__device__ int d_overflow[BATCH];
__device__ u64 d_fin[(size_t)BATCH * FINCAP];
__device__ int d_finN[BATCH];
__device__ int d_ok[BATCH];
// fallback path
__device__ float  d_candScore[(size_t)BATCH * NCAND];
__device__ int    d_candAnchor[(size_t)BATCH * NCAND];
__device__ float4 d_candBox[(size_t)BATCH * NCAND];

__device__ __forceinline__ u32 fmono(float f) {
    u32 u = __float_as_uint(f);
    return u ^ ((u >> 31) ? 0xFFFFFFFFu : 0x80000000u);
}

__global__ void k_init() {
    int i = blockIdx.x * 1024 + threadIdx.x;
    if (i < BATCH * NC) d_selN[i] = 0;
    if (i < BATCH) {
        d_capmax[i] = fmono(T0) + 16;   // excluded p <= 0.07*(1+2^-22) < this
        d_overflow[i] = 0; d_finN[i] = 0; d_ok[i] = 0;
    }
}

// ================= Kernel 1: softmax (XLA:GPU warp order) + decode + emit ===
// FROZEN FP ARITHMETIC: max/exp/sum trees and __fdiv_rn scores bitwise-match
// the reference lowering. Emission set {e > RN(s*T0)} is score-downward-closed;
// exactness is verified downstream (capmax / s200 / overflow -> fallback).
__global__ void __launch_bounds__(1024) k_softmax_decode(
        const float* __restrict__ logits,
        const float* __restrict__ reg,
        const float* __restrict__ anchors) {
    int w = threadIdx.x >> 5, lane = threadIdx.x & 31;
    long flat = (long)blockIdx.x * 32 + w;
    size_t lbase = (size_t)flat * NCLASS;
    int b0 = (int)((blockIdx.x * 32) / NA);
    int a0 = (int)(blockIdx.x * 32 - b0 * NA);
    int aw = a0 + w, bw = b0;
    if (aw >= NA) { aw -= NA; bw++; }

    float x0 = logits[lbase + lane];
    float x1 = logits[lbase + lane + 32];
    float x2 = (lane < 27) ? logits[lbase + lane + 64] : NEG_INF;

    float m = fmaxf(fmaxf(x0, x1), x2);
    #pragma unroll
    for (int o = 16; o; o >>= 1) m = fmaxf(m, __shfl_down_sync(0xffffffffu, m, o));
    m = __shfl_sync(0xffffffffu, m, 0);

    float e0 = expf(x0 - m), e1 = expf(x1 - m), e2 = expf(x2 - m);
    float s = __fadd_rn(__fadd_rn(e0, e1), e2);
    #pragma unroll
    for (int o = 16; o; o >>= 1) s = __fadd_rn(s, __shfl_down_sync(0xffffffffu, s, o));
    s = __shfl_sync(0xffffffffu, s, 0);

    float thr = __fmul_rn(s, T0);
    // emit candidates: class c0=lane-1, c1=lane+31, c2=lane+63
    #pragma unroll
    for (int r = 0; r < 3; r++) {
        float e = (r == 0) ? e0 : (r == 1) ? e1 : e2;
        int c  = (r == 0) ? lane - 1 : (r == 1) ? lane + 31 : lane + 63;
        bool valid = (r == 0) ? (lane >= 1) : (r == 1) ? true : (lane < 27);
        if (valid && e > thr) {
            float p = __fdiv_rn(e, s);               // frozen exact score
            u64 key = ((u64)fmono(p) << 14) | (u64)(0x3FFFu - (u32)aw);
            int bc = bw * NC + c;
            int idx = atomicAdd(&d_selN[bc], 1);
            if (idx < BCAP) d_selKey[(size_t)bc * BCAP + idx] = key;
            else d_overflow[bw] = 1;
        }
    }

    if (threadIdx.x < 32) {
        int a = a0 + threadIdx.x, b = b0;
        if (a >= NA) { a -= NA; b++; }
        long fl = (long)blockIdx.x * 32 + threadIdx.x;
        float4 rg = ((const float4*)reg)[fl];
        float4 an = ((const float4*)anchors)[a];
        float wa = __fsub_rn(an.z, an.x), ha = __fsub_rn(an.w, an.y);
        float cxa = __fadd_rn(an.x, __fmul_rn(0.5f, wa));
        float cya = __fadd_rn(an.y, __fmul_rn(0.5f, ha));
        float dx = __fdiv_rn(rg.x, 10.0f), dy = __fdiv_rn(rg.y, 10.0f);
        float dw = fminf(__fdiv_rn(rg.z, 5.0f), BBOX_CLIP);
        float dh = fminf(__fdiv_rn(rg.w, 5.0f), BBOX_CLIP);
        float cx = __fadd_rn(__fmul_rn(dx, wa), cxa);
        float cy = __fadd_rn(__fmul_rn(dy, ha), cya);
        float bwd = __fmul_rn(expf(dw), wa), bhd = __fmul_rn(expf(dh), ha);
        float hw = __fmul_rn(0.5f, bwd), hh = __fmul_rn(0.5f, bhd);
        float4 bx;
        bx.x = fminf(fmaxf(__fsub_rn(cx, hw), 0.f), IMGSZ);
        bx.y = fminf(fmaxf(__fsub_rn(cy, hh), 0.f), IMGSZ);
        bx.z = fminf(fmaxf(__fadd_rn(cx, hw), 0.f), IMGSZ);
        bx.w = fminf(fmaxf(__fadd_rn(cy, hh), 0.f), IMGSZ);
        d_dboxes[(size_t)b * NA + a] = bx;
    }
}

// ---- warp-register bitonic helpers (128 u64, 4/lane, descending) ----
__device__ __forceinline__ u64 ce_shfl(u64 x, int j2, bool dird, int lane) {
    u64 y = __shfl_xor_sync(0xffffffffu, x, j2);
    bool lower = (lane & j2) == 0;
    bool keepmax = (dird == lower);
    u64 mx = (x > y) ? x : y;
    u64 mn = (x > y) ? y : x;
    return keepmax ? mx : mn;
}

// ===== Kernel 2: per-(b,c) warp-sort<=128 + greedy NMS + emit survivors =====
__global__ void __launch_bounds__(128) k_nms_fast() {
    int bc = blockIdx.x;
    int b = bc / NC, c = bc % NC;
    int n = min(d_selN[bc], BCAP);
    if (n == 0) return;
    int t = threadIdx.x;

    __shared__ u64   s_key[128];
    __shared__ float4 s_bx[BCAP];
    __shared__ float  s_ar[BCAP];
    __shared__ u64   s_m0[BCAP], s_m1[BCAP];
    __shared__ u64   s_alive[2], s_hk[2];

    if (t < 2) { s_alive[t] = 0ull; s_hk[t] = 0ull; }

    if (t < 32) {
        int lane = t;
        u64 v[4];
        #pragma unroll
        for (int r = 0; r < 4; r++) {
            int i = r * 32 + lane;
            v[r] = (i < n) ? d_selKey[(size_t)bc * BCAP + i] : 0ull;
        }
        #pragma unroll
        for (int k = 2; k <= 128; k <<= 1) {
            #pragma unroll
            for (int j2 = 64; j2 >= 1; j2 >>= 1) {
                if (j2 > (k >> 1)) continue;
                if (j2 >= 32) {
                    int rstep = j2 >> 5;
                    #pragma unroll
                    for (int r = 0; r < 4; r++) {
                        if ((r & rstep) == 0) {
                            int i = r * 32 + lane;
                            bool dird = ((i & k) == 0);
                            u64 lo2 = v[r], hi2 = v[r + rstep];
                            bool sw = dird ? (lo2 < hi2) : (lo2 > hi2);
                            if (sw) { v[r] = hi2; v[r + rstep] = lo2; }
                        }
                    }
                } else {
                    #pragma unroll
                    for (int r = 0; r < 4; r++) {
                        int i = r * 32 + lane;
                        bool dird = ((i & k) == 0);
                        v[r] = ce_shfl(v[r], j2, dird, lane);
                    }
                }
            }
        }
        #pragma unroll
        for (int r = 0; r < 4; r++) s_key[r * 32 + lane] = v[r];
    }
    __syncthreads();

    u64 v = s_key[t];
    u32 key32 = (u32)(v >> 14);
    int anchor = (int)(0x3FFFu - (u32)(v & 0x3FFF));
    float off = __fmul_rn((float)(c + 1), IMGSZ + 1.0f);
    if (t < n) {
        float4 raw = d_dboxes[(size_t)b * NA + anchor];
        float4 bx;
        bx.x = __fadd_rn(raw.x, off);
        bx.y = __fadd_rn(raw.y, off);
        bx.z = __fadd_rn(raw.z, off);
        bx.w = __fadd_rn(raw.w, off);
        s_bx[t] = bx;
        s_ar[t] = __fmul_rn(__fsub_rn(bx.z, bx.x), __fsub_rn(bx.w, bx.y));
        atomicOr(&s_alive[t >> 6], 1ull << (t & 63));
    }
    __syncthreads();

    if (t < n) {
        float4 bi = s_bx[t];
        float ai = s_ar[t];
        u64 m0 = 0ull, m1 = 0ull;
        for (int j = t + 1; j < n; j++) {
            float4 bj = s_bx[j];
            float lx = fmaxf(bi.x, bj.x), ly = fmaxf(bi.y, bj.y);
            float rx = fminf(bi.z, bj.z), ry = fminf(bi.w, bj.w);
            float iw = fmaxf(__fsub_rn(rx, lx), 0.f);
            float ih = fmaxf(__fsub_rn(ry, ly), 0.f);
            float inter = __fmul_rn(iw, ih);
            bool kill = false;
            if (inter > 0.f) {
                float den = __fadd_rn(__fsub_rn(__fadd_rn(ai, s_ar[j]), inter), 1e-9f);
                kill = (__fdiv_rn(inter, den) > NMS_T);
            }
            if (j < 64) m0 |= ((u64)kill) << j;
            else        m1 |= ((u64)kill) << (j - 64);
        }
        s_m0[t] = m0; s_m1[t] = m1;
        if (m0 | m1) atomicOr(&s_hk[t >> 6], 1ull << (t & 63));
    }
    __syncthreads();

    if (t == 0) {
        u64 a0 = s_alive[0], a1 = s_alive[1];
        #pragma unroll
        for (int w = 0; w < 2; w++) {
            u64 rem = s_hk[w];
            while (rem) {
                int bit = __ffsll((long long)rem) - 1;
                rem &= rem - 1;
                u64 ab = (w == 0) ? a0 : a1;
                if ((ab >> bit) & 1ull) {
                    int i = (w << 6) + bit;
                    a0 &= ~s_m0[i]; a1 &= ~s_m1[i];
                }
            }
        }
        s_alive[0] = a0; s_alive[1] = a1;
    }
    __syncthreads();

    if (t < n) {
        bool al = (s_alive[t >> 6] >> (t & 63)) & 1ull;
        if (al) {
            u64 fk = ((u64)key32 << 21) | ((u64)(0x7Fu - (u32)c) << 14)
                   | (u64)(0x3FFFu - (u32)anchor);
            int p = atomicAdd(&d_finN[b], 1);
            if (p < FINCAP) d_fin[(size_t)b * FINCAP + p] = fk;
            else d_overflow[b] = 1;
        }
    }
}

// ===== Kernel 3: per-image final top-200 (score desc, cls asc, anchor asc) =====
__global__ void __launch_bounds__(1024) k_out_fast(float* __restrict__ out) {
    extern __shared__ u64 s_f[];          // FINCAP u64 = 72 KB
    __shared__ u64 buf[512];
    __shared__ int s_cnt, s_n, s_okflag;
    int b = blockIdx.x, t = threadIdx.x;
    int n = min(d_finN[b], FINCAP);

    #pragma unroll
    for (int k = 0; k < 9; k++) {
        int i = t + (k << 10);
        s_f[i] = (i < n) ? d_fin[(size_t)b * FINCAP + i] : 0ull;
    }
    if (t < 512) buf[t] = 0ull;
    __syncthreads();

    u32 tau = TAU_MIN;
    int ovf = d_overflow[b];
    if (n > 448) {
        u64 lo = (u64)TAU_MIN + 1, hi = 0xBF800000ull;
        int cntb = n;
        while (lo <= hi) {
            u32 mid = (u32)(lo + ((hi - lo) >> 1));
            if (t == 0) s_cnt = 0;
            __syncthreads();
            int cl = 0;
            #pragma unroll
            for (int k = 0; k < 9; k++)
                cl += ((u32)(s_f[t + (k << 10)] >> 21) >= mid);
            #pragma unroll
            for (int o = 16; o; o >>= 1) cl += __shfl_down_sync(0xffffffffu, cl, o);
            if ((t & 31) == 0) atomicAdd(&s_cnt, cl);
            __syncthreads();
            int cn = s_cnt;
            __syncthreads();
            if (cn >= MAXDET) {
                tau = mid; cntb = cn; lo = (u64)mid + 1;
                if (cn <= 448) break;
            } else hi = (u64)mid - 1;
        }
        if (cntb > 448) ovf = 1;
    }

    if (t == 0) s_n = 0;
    __syncthreads();
    #pragma unroll
    for (int k = 0; k < 9; k++) {
        u64 v = s_f[t + (k << 10)];
        if (v != 0ull && (u32)(v >> 21) >= tau) {
            int p = atomicAdd(&s_n, 1);
            if (p < 512) buf[p] = v;
        }
    }
    __syncthreads();

    for (int k = 2; k <= 512; k <<= 1) {
        for (int j2 = k >> 1; j2 > 0; j2 >>= 1) {
            if (t < 512) {
                int ixj = t ^ j2;
                if (ixj > t) {
                    u64 x = buf[t], y = buf[ixj];
                    bool sw = ((t & k) == 0) ? (x < y) : (x > y);
                    if (sw) { buf[t] = y; buf[ixj] = x; }
                }
            }
            __syncthreads();
        }
    }

    if (t == 0) {
        u64 v199 = buf[MAXDET - 1];
        u32 s200 = (u32)(v199 >> 21);
        u32 cm = d_capmax[b];
        int ok = (!ovf) && (s200 > cm);
        s_okflag = ok;
        d_ok[b] = ok;
    }
    __syncthreads();

    if (s_okflag && t < MAXDET) {
        u64 v = buf[t];
        float4 bx = make_float4(0.f, 0.f, 0.f, 0.f);
        float so = 0.f, lb = 0.f;
        if (v != 0ull) {
            u32 key32 = (u32)(v >> 21);
            int cls = (int)(0x7Fu - ((u32)(v >> 14) & 0x7Fu));
            int anchor = (int)(0x3FFFu - (u32)(v & 0x3FFF));
            so = __uint_as_float(key32 ^ 0x80000000u);
            bx = d_dboxes[(size_t)b * NA + anchor];
            lb = (float)(cls + 1);
        }
        size_t ob = ((size_t)b * MAXDET + t) * 4;
        out[ob + 0] = bx.x; out[ob + 1] = bx.y;
        out[ob + 2] = bx.z; out[ob + 3] = bx.w;
        out[(size_t)BATCH * MAXDET * 4 + (size_t)b * MAXDET + t] = so;
        out[(size_t)BATCH * MAXDET * 5 + (size_t)b * MAXDET + t] = lb;
    }
}

// ================= FALLBACK (proven R8 path, gated on !d_ok[b]) =============
// Step 0: regenerate d_probs for failed images (old k1 softmax, frozen math).
__global__ void __launch_bounds__(1024) k_probs_fb(const float* __restrict__ logits) {
    int bA = (int)((blockIdx.x * 32) / NA);
    int bB = (int)((blockIdx.x * 32 + 31) / NA);
    if (d_ok[bA] && d_ok[bB]) return;

    __shared__ float s_p[NC][33];
    int w = threadIdx.x >> 5, lane = threadIdx.x & 31;
    long flat = (long)blockIdx.x * 32 + w;
    size_t lbase = (size_t)flat * NCLASS;
    int a0 = (int)(blockIdx.x * 32 - bA * NA);

    float x0 = logits[lbase + lane];
    float x1 = logits[lbase + lane + 32];
    float x2 = (lane < 27) ? logits[lbase + lane + 64] : NEG_INF;

    float m = fmaxf(fmaxf(x0, x1), x2);
    #pragma unroll
    for (int o = 16; o; o >>= 1) m = fmaxf(m, __shfl_down_sync(0xffffffffu, m, o));
    m = __shfl_sync(0xffffffffu, m, 0);

    float e0 = expf(x0 - m), e1 = expf(x1 - m), e2 = expf(x2 - m);
    float s = __fadd_rn(__fadd_rn(e0, e1), e2);
    #pragma unroll
    for (int o = 16; o; o >>= 1) s = __fadd_rn(s, __shfl_down_sync(0xffffffffu, s, o));
    s = __shfl_sync(0xffffffffu, s, 0);

    if (lane >= 1) {
        float p = __fdiv_rn(e0, s);
        s_p[lane - 1][w] = (p > SCORE_T) ? p : NEG_INF;
    }
    {
        float p = __fdiv_rn(e1, s);
        s_p[lane + 31][w] = (p > SCORE_T) ? p : NEG_INF;
    }
    if (lane < 27) {
        float p = __fdiv_rn(e2, s);
        s_p[lane + 63][w] = (p > SCORE_T) ? p : NEG_INF;
    }
    __syncthreads();

    #pragma unroll
    for (int i = threadIdx.x; i < NC * 32; i += 1024) {
        int c = i >> 5, wl = i & 31;
        int a = a0 + wl, b = bA;
        if (a >= NA) { a -= NA; b++; }
        d_probs[((size_t)b * NC + c) * NA + a] = s_p[c][wl];
    }
}

#define TKTHREADS 512
#define TKCAP 512
#define NLOC 18

__global__ void __launch_bounds__(TKTHREADS) k_topk_fb() {
    int b = blockIdx.x / NC, c = blockIdx.x % NC;
    if (d_ok[b]) return;
    const float* sc = &d_probs[((size_t)b * NC + c) * NA];
    int t = threadIdx.x;

    u32 key[NLOC];
    #pragma unroll
    for (int j = 0; j < NLOC; j++) {
        int idx = j * TKTHREADS + t;
        float v = (idx < NA) ? sc[idx] : -1.0f;
        key[j] = (idx < NA && v > SCORE_T) ? fmono(v) : 0u;
    }

    __shared__ int s_cnt;
    u64 lo = 0xBC23D70Bull, hi = 0xBF800000ull;
    u32 tau = 0;
    while (lo <= hi) {
        u32 mid = (u32)(lo + ((hi - lo) >> 1));
        if (t == 0) s_cnt = 0;
        __syncthreads();
        int cl = 0;
        #pragma unroll
        for (int j = 0; j < NLOC; j++) cl += (key[j] >= mid);
        #pragma unroll
        for (int o = 16; o; o >>= 1) cl += __shfl_down_sync(0xffffffffu, cl, o);
        if ((t & 31) == 0) atomicAdd(&s_cnt, cl);
        __syncthreads();
        int cnt = s_cnt;
        __syncthreads();
        if (cnt >= KTOP) { tau = mid; lo = (u64)mid + 1; }
        else             { hi = (u64)mid - 1; }
    }

    __shared__ u64 buf[TKCAP];
    __shared__ int s_n;
    if (t == 0) s_n = 0;
    if (t < TKCAP) buf[t] = 0ull;
    __syncthreads();
    #pragma unroll
    for (int j = 0; j < NLOC; j++) {
        if (key[j] != 0u && key[j] >= tau) {
            int p = atomicAdd(&s_n, 1);
            if (p < TKCAP) {
                u32 anchor = (u32)(j * TKTHREADS + t);
                buf[p] = ((u64)key[j] << 32) | (u64)(0xFFFFFFFFu - anchor);
            }
        }
    }
    __syncthreads();

    for (int k = 2; k <= TKCAP; k <<= 1) {
        for (int j2 = k >> 1; j2 > 0; j2 >>= 1) {
            if (t < TKCAP) {
                int ixj = t ^ j2;
                if (ixj > t) {
                    u64 x = buf[t], y = buf[ixj];
                    bool sw = ((t & k) == 0) ? (x < y) : (x > y);
                    if (sw) { buf[t] = y; buf[ixj] = x; }
                }
            }
            __syncthreads();
        }
    }

    int nv = min(s_n, TKCAP);
    size_t obase = (size_t)b * NCAND + (size_t)c * KTOP;
    float off = __fmul_rn((float)(c + 1), IMGSZ + 1.0f);
    if (t < KTOP) {
        float scv = NEG_INF;
        int anc = 0;
        if (t < nv) {
            u64 v = buf[t];
            u32 h32 = (u32)(v >> 32);
            scv = __uint_as_float(h32 ^ 0x80000000u);
            anc = (int)(0xFFFFFFFFu - (u32)v);
        }
        d_candScore[obase + t]  = scv;
        d_candAnchor[obase + t] = anc;
        float4 raw = d_dboxes[(size_t)b * NA + anc];
        float4 ob;
        ob.x = __fadd_rn(raw.x, off);
        ob.y = __fadd_rn(raw.y, off);
        ob.z = __fadd_rn(raw.z, off);
        ob.w = __fadd_rn(raw.w, off);
        d_candBox[obase + t] = ob;
    }
}

__global__ void __launch_bounds__(416) k_nms_fb() {
    int b = blockIdx.x / NC, c = blockIdx.x % NC;
    if (d_ok[b]) return;
    __shared__ float  s_sc[KTOP];
    __shared__ float4 s_bx[KTOP];
    __shared__ float  s_ar[KTOP];
    __shared__ int    s_alive[KTOP];
    int t = threadIdx.x;
    size_t base = (size_t)b * NCAND + (size_t)c * KTOP;

    float4 my = make_float4(0.f, 0.f, 0.f, 0.f);
    float mya = 0.f;
    if (t < KTOP) {
        float s = d_candScore[base + t];
        float4 bx = d_candBox[base + t];
        s_sc[t] = s;
        s_bx[t] = bx;
        float ar = __fmul_rn(__fsub_rn(bx.z, bx.x), __fsub_rn(bx.w, bx.y));
        s_ar[t] = ar;
        s_alive[t] = isfinite(s) ? 1 : 0;
        my = bx; mya = ar;
    }
    __syncthreads();

    for (int i = 0; i < KTOP; i++) {
        if (s_alive[i]) {
            if (t > i && t < KTOP && s_alive[t]) {
                float4 bi = s_bx[i];
                float lx = fmaxf(bi.x, my.x), ly = fmaxf(bi.y, my.y);
                float rx = fminf(bi.z, my.z), ry = fminf(bi.w, my.w);
                float iw = fmaxf(__fsub_rn(rx, lx), 0.f);
                float ih = fmaxf(__fsub_rn(ry, ly), 0.f);
                float inter = __fmul_rn(iw, ih);
                float den = __fadd_rn(__fsub_rn(__fadd_rn(s_ar[i], mya), inter), 1e-9f);
                float iou = __fdiv_rn(inter, den);
                if (iou > NMS_T) s_alive[t] = 0;
            }
            __syncthreads();
        }
    }
    __syncthreads();
    if (t < KTOP)
        d_candScore[base + t] = s_alive[t] ? s_sc[t] : NEG_INF;
}

#define SELPAD 36864
__global__ void __launch_bounds__(1024) k_select_fb(float* __restrict__ out) {
    int b = blockIdx.x, t = threadIdx.x;
    if (d_ok[b]) return;
    extern __shared__ u32 s_key2[];
    __shared__ u64 buf[512];
    __shared__ int s_cnt, s_n;

    for (int i = t; i < NCAND; i += 1024) {
        float v = d_candScore[(size_t)b * NCAND + i];
        s_key2[i] = isfinite(v) ? fmono(v) : 0u;
    }
    for (int i = NCAND + t; i < SELPAD; i += 1024) s_key2[i] = 0u;
    if (t < 512) buf[t] = 0ull;

    u64 lo = 0xBC23D70Bull, hi = 0xBF800000ull;
    u32 tau = 0;
    const uint4* k4 = (const uint4*)s_key2;
    __syncthreads();
    while (lo <= hi) {
        u32 mid = (u32)(lo + ((hi - lo) >> 1));
        if (t == 0) s_cnt = 0;
        __syncthreads();
        int cl = 0;
        #pragma unroll
        for (int k = 0; k < 9; k++) {
            uint4 v = k4[t + (k << 10)];
            cl += (v.x >= mid) + (v.y >= mid) + (v.z >= mid) + (v.w >= mid);
        }
        #pragma unroll
        for (int o = 16; o; o >>= 1) cl += __shfl_down_sync(0xffffffffu, cl, o);
        if ((t & 31) == 0) atomicAdd(&s_cnt, cl);
        __syncthreads();
        int cnt = s_cnt;
        __syncthreads();
        if (cnt >= MAXDET) { tau = mid; lo = (u64)mid + 1; }
        else               { hi = (u64)mid - 1; }
    }
    if (t == 0) s_n = 0;
    __syncthreads();
    #pragma unroll
    for (int k = 0; k < 36; k++) {
        int i = t + (k << 10);
        if (i < NCAND) {
            u32 kv = s_key2[i];
            if (kv >= tau) {
                int p = atomicAdd(&s_n, 1);
                if (p < 512)
                    buf[p] = ((u64)kv << 32) | (u64)(0xFFFFFFFFu - (u32)i);
            }
        }
    }
    __syncthreads();

    for (int k = 2; k <= 512; k <<= 1) {
        for (int j2 = k >> 1; j2 > 0; j2 >>= 1) {
            if (t < 512) {
                int ixj = t ^ j2;
                if (ixj > t) {
                    u64 x = buf[t], y = buf[ixj];
                    bool sw = ((t & k) == 0) ? (x < y) : (x > y);
                    if (sw) { buf[t] = y; buf[ixj] = x; }
                }
            }
            __syncthreads();
        }
    }

    if (t < MAXDET) {
        u64 v = buf[t];
        u32 h = (u32)(v >> 32);
        float4 bx = make_float4(0.f, 0.f, 0.f, 0.f);
        float so = 0.f, lb = 0.f;
        if (h != 0u) {
            int idx = (int)(0xFFFFFFFFu - (u32)v);
            so = __uint_as_float(h ^ 0x80000000u);
            int cls = idx / KTOP;
            int anc = d_candAnchor[(size_t)b * NCAND + idx];
            bx = d_dboxes[(size_t)b * NA + anc];
            lb = (float)(cls + 1);
        }
        size_t ob = ((size_t)b * MAXDET + t) * 4;
        out[ob + 0] = bx.x; out[ob + 1] = bx.y;
        out[ob + 2] = bx.z; out[ob + 3] = bx.w;
        out[(size_t)BATCH * MAXDET * 4 + (size_t)b * MAXDET + t] = so;
        out[(size_t)BATCH * MAXDET * 5 + (size_t)b * MAXDET + t] = lb;
    }
}

// ================= host =================
extern "C" void kernel_launch(void* const* d_in, const int* in_sizes, int n_in,
                              void* d_out, int out_size) {
    const float* logits  = (const float*)d_in[0];
    const float* reg     = (const float*)d_in[1];
    const float* anchors = (const float*)d_in[2];
    float* out = (float*)d_out;

    k_init<<<3, 1024>>>();
    k_softmax_decode<<<(BATCH * NA) / 32, 1024>>>(logits, reg, anchors);
    k_nms_fast<<<BATCH * NC, 128>>>();
    cudaFuncSetAttribute(k_out_fast, cudaFuncAttributeMaxDynamicSharedMemorySize,
                         FINCAP * (int)sizeof(u64));
    k_out_fast<<<BATCH, 1024, FINCAP * sizeof(u64)>>>(out);
    // fallback chain (no-ops when fast path verified exact)
    k_probs_fb<<<(BATCH * NA) / 32, 1024>>>(logits);
    k_topk_fb<<<BATCH * NC, TKTHREADS>>>();
    k_nms_fb<<<BATCH * NC, 416>>>();
    cudaFuncSetAttribute(k_select_fb, cudaFuncAttributeMaxDynamicSharedMemorySize,
                         SELPAD * (int)sizeof(u32));
    k_select_fb<<<BATCH, 1024, SELPAD * sizeof(u32)>>>(out);
}

// round 15
// speedup vs baseline: 2.0867x; 1.5153x over previous
#include <cuda_runtime.h>

#define BATCH   32
#define NA      8732
#define NCLASS  91
#define NC      90
#define KTOP    400
#define NCAND   (NC * KTOP)      /* 36000 */
#define MAXDET  200
#define IMGSZ   300.0f
#define SCORE_T 0.01f
#define NMS_T   0.45f
#define BBOX_CLIP 4.135166556742356f
#define NEG_INF __int_as_float(0xff800000)
#define TAU_MIN 0xBC23D70Cu      /* fmono(0.01f)+1 */
#define T0      0.12f            /* fixed emission threshold (verified safe) */
#define BCAP    128              /* bucket capacity per (b,c) */
#define FINCAP  9216

typedef unsigned long long u64;
typedef unsigned u32;

// -------- scratch (device globals; no allocations allowed) --------
__device__ float  d_probs[(size_t)BATCH * NC * NA];      // fallback only
__device__ float4 d_dboxes[(size_t)BATCH * NA];
// fast path
__device__ u64 d_selKey[(size_t)BATCH * NC * BCAP];
__device__ int d_selN[BATCH * NC];
__device__ u32 d_capmax[BATCH];
__device__ int d_overflow[BATCH];
__device__ u64 d_fin[(size_t)BATCH * FINCAP];
__device__ int d_finN[BATCH];
__device__ int d_ok[BATCH];
// fallback path
__device__ float  d_candScore[(size_t)BATCH * NCAND];
__device__ int    d_candAnchor[(size_t)BATCH * NCAND];
__device__ float4 d_candBox[(size_t)BATCH * NCAND];

__device__ __forceinline__ u32 fmono(float f) {
    u32 u = __float_as_uint(f);
    return u ^ ((u >> 31) ? 0xFFFFFFFFu : 0x80000000u);
}

__global__ void k_init() {
    int i = blockIdx.x * 1024 + threadIdx.x;
    if (i < BATCH * NC) d_selN[i] = 0;
    if (i < BATCH) {
        d_capmax[i] = fmono(T0) + 16;   // excluded p <= T0*(1+2^-22) < this
        d_overflow[i] = 0; d_finN[i] = 0; d_ok[i] = 0;
    }
}

// ================= Kernel 1: softmax (XLA:GPU warp order) + decode + emit ===
// FROZEN FP ARITHMETIC: max/exp/sum trees and __fdiv_rn scores bitwise-match
// the reference lowering. Emission set {e > RN(s*T0)} is score-downward-closed;
// exactness is verified downstream (capmax / s200 / overflow -> fallback).
__global__ void __launch_bounds__(1024) k_softmax_decode(
        const float* __restrict__ logits,
        const float* __restrict__ reg,
        const float* __restrict__ anchors) {
    int w = threadIdx.x >> 5, lane = threadIdx.x & 31;
    long flat = (long)blockIdx.x * 32 + w;
    size_t lbase = (size_t)flat * NCLASS;
    int b0 = (int)((blockIdx.x * 32) / NA);
    int a0 = (int)(blockIdx.x * 32 - b0 * NA);
    int aw = a0 + w, bw = b0;
    if (aw >= NA) { aw -= NA; bw++; }

    float x0 = logits[lbase + lane];
    float x1 = logits[lbase + lane + 32];
    float x2 = (lane < 27) ? logits[lbase + lane + 64] : NEG_INF;

    float m = fmaxf(fmaxf(x0, x1), x2);
    #pragma unroll
    for (int o = 16; o; o >>= 1) m = fmaxf(m, __shfl_down_sync(0xffffffffu, m, o));
    m = __shfl_sync(0xffffffffu, m, 0);

    float e0 = expf(x0 - m), e1 = expf(x1 - m), e2 = expf(x2 - m);
    float s = __fadd_rn(__fadd_rn(e0, e1), e2);
    #pragma unroll
    for (int o = 16; o; o >>= 1) s = __fadd_rn(s, __shfl_down_sync(0xffffffffu, s, o));
    s = __shfl_sync(0xffffffffu, s, 0);

    float thr = __fmul_rn(s, T0);
    #pragma unroll
    for (int r = 0; r < 3; r++) {
        float e = (r == 0) ? e0 : (r == 1) ? e1 : e2;
        int c  = (r == 0) ? lane - 1 : (r == 1) ? lane + 31 : lane + 63;
        bool valid = (r == 0) ? (lane >= 1) : (r == 1) ? true : (lane < 27);
        if (valid && e > thr) {
            float p = __fdiv_rn(e, s);               // frozen exact score
            u64 key = ((u64)fmono(p) << 14) | (u64)(0x3FFFu - (u32)aw);
            int bc = bw * NC + c;
            int idx = atomicAdd(&d_selN[bc], 1);
            if (idx < BCAP) d_selKey[(size_t)bc * BCAP + idx] = key;
            else d_overflow[bw] = 1;
        }
    }

    if (threadIdx.x < 32) {
        int a = a0 + threadIdx.x, b = b0;
        if (a >= NA) { a -= NA; b++; }
        long fl = (long)blockIdx.x * 32 + threadIdx.x;
        float4 rg = ((const float4*)reg)[fl];
        float4 an = ((const float4*)anchors)[a];
        float wa = __fsub_rn(an.z, an.x), ha = __fsub_rn(an.w, an.y);
        float cxa = __fadd_rn(an.x, __fmul_rn(0.5f, wa));
        float cya = __fadd_rn(an.y, __fmul_rn(0.5f, ha));
        float dx = __fdiv_rn(rg.x, 10.0f), dy = __fdiv_rn(rg.y, 10.0f);
        float dw = fminf(__fdiv_rn(rg.z, 5.0f), BBOX_CLIP);
        float dh = fminf(__fdiv_rn(rg.w, 5.0f), BBOX_CLIP);
        float cx = __fadd_rn(__fmul_rn(dx, wa), cxa);
        float cy = __fadd_rn(__fmul_rn(dy, ha), cya);
        float bwd = __fmul_rn(expf(dw), wa), bhd = __fmul_rn(expf(dh), ha);
        float hw = __fmul_rn(0.5f, bwd), hh = __fmul_rn(0.5f, bhd);
        float4 bx;
        bx.x = fminf(fmaxf(__fsub_rn(cx, hw), 0.f), IMGSZ);
        bx.y = fminf(fmaxf(__fsub_rn(cy, hh), 0.f), IMGSZ);
        bx.z = fminf(fmaxf(__fadd_rn(cx, hw), 0.f), IMGSZ);
        bx.w = fminf(fmaxf(__fadd_rn(cy, hh), 0.f), IMGSZ);
        d_dboxes[(size_t)b * NA + a] = bx;
    }
}

// ---- warp-register bitonic helpers (128 u64, 4/lane, descending) ----
__device__ __forceinline__ u64 ce_shfl(u64 x, int j2, bool dird, int lane) {
    u64 y = __shfl_xor_sync(0xffffffffu, x, j2);
    bool lower = (lane & j2) == 0;
    bool keepmax = (dird == lower);
    u64 mx = (x > y) ? x : y;
    u64 mn = (x > y) ? y : x;
    return keepmax ? mx : mn;
}

// ===== Kernel 2: per-(b,c) warp-sort<=128 + greedy NMS + emit survivors =====
__global__ void __launch_bounds__(128) k_nms_fast() {
    int bc = blockIdx.x;
    int b = bc / NC, c = bc % NC;
    int n = min(d_selN[bc], BCAP);
    if (n == 0) return;
    int t = threadIdx.x;

    __shared__ u64   s_key[128];
    __shared__ float4 s_bx[BCAP];
    __shared__ float  s_ar[BCAP];
    __shared__ u64   s_m0[BCAP], s_m1[BCAP];
    __shared__ u64   s_alive[2], s_hk[2];

    if (t < 2) { s_alive[t] = 0ull; s_hk[t] = 0ull; }

    if (t < 32) {
        int lane = t;
        u64 v[4];
        #pragma unroll
        for (int r = 0; r < 4; r++) {
            int i = r * 32 + lane;
            v[r] = (i < n) ? d_selKey[(size_t)bc * BCAP + i] : 0ull;
        }
        #pragma unroll
        for (int k = 2; k <= 128; k <<= 1) {
            #pragma unroll
            for (int j2 = 64; j2 >= 1; j2 >>= 1) {
                if (j2 > (k >> 1)) continue;
                if (j2 >= 32) {
                    int rstep = j2 >> 5;
                    #pragma unroll
                    for (int r = 0; r < 4; r++) {
                        if ((r & rstep) == 0) {
                            int i = r * 32 + lane;
                            bool dird = ((i & k) == 0);
                            u64 lo2 = v[r], hi2 = v[r + rstep];
                            bool sw = dird ? (lo2 < hi2) : (lo2 > hi2);
                            if (sw) { v[r] = hi2; v[r + rstep] = lo2; }
                        }
                    }
                } else {
                    #pragma unroll
                    for (int r = 0; r < 4; r++) {
                        int i = r * 32 + lane;
                        bool dird = ((i & k) == 0);
                        v[r] = ce_shfl(v[r], j2, dird, lane);
                    }
                }
            }
        }
        #pragma unroll
        for (int r = 0; r < 4; r++) s_key[r * 32 + lane] = v[r];
    }
    __syncthreads();

    u64 v = s_key[t];
    u32 key32 = (u32)(v >> 14);
    int anchor = (int)(0x3FFFu - (u32)(v & 0x3FFF));
    float off = __fmul_rn((float)(c + 1), IMGSZ + 1.0f);
    if (t < n) {
        float4 raw = d_dboxes[(size_t)b * NA + anchor];
        float4 bx;
        bx.x = __fadd_rn(raw.x, off);
        bx.y = __fadd_rn(raw.y, off);
        bx.z = __fadd_rn(raw.z, off);
        bx.w = __fadd_rn(raw.w, off);
        s_bx[t] = bx;
        s_ar[t] = __fmul_rn(__fsub_rn(bx.z, bx.x), __fsub_rn(bx.w, bx.y));
        atomicOr(&s_alive[t >> 6], 1ull << (t & 63));
    }
    __syncthreads();

    if (t < n) {
        float4 bi = s_bx[t];
        float ai = s_ar[t];
        u64 m0 = 0ull, m1 = 0ull;
        for (int j = t + 1; j < n; j++) {
            float4 bj = s_bx[j];
            float lx = fmaxf(bi.x, bj.x), ly = fmaxf(bi.y, bj.y);
            float rx = fminf(bi.z, bj.z), ry = fminf(bi.w, bj.w);
            float iw = fmaxf(__fsub_rn(rx, lx), 0.f);
            float ih = fmaxf(__fsub_rn(ry, ly), 0.f);
            float inter = __fmul_rn(iw, ih);
            bool kill = false;
            if (inter > 0.f) {
                float den = __fadd_rn(__fsub_rn(__fadd_rn(ai, s_ar[j]), inter), 1e-9f);
                kill = (__fdiv_rn(inter, den) > NMS_T);
            }
            if (j < 64) m0 |= ((u64)kill) << j;
            else        m1 |= ((u64)kill) << (j - 64);
        }
        s_m0[t] = m0; s_m1[t] = m1;
        if (m0 | m1) atomicOr(&s_hk[t >> 6], 1ull << (t & 63));
    }
    __syncthreads();

    if (t == 0) {
        u64 a0 = s_alive[0], a1 = s_alive[1];
        #pragma unroll
        for (int w = 0; w < 2; w++) {
            u64 rem = s_hk[w];
            while (rem) {
                int bit = __ffsll((long long)rem) - 1;
                rem &= rem - 1;
                u64 ab = (w == 0) ? a0 : a1;
                if ((ab >> bit) & 1ull) {
                    int i = (w << 6) + bit;
                    a0 &= ~s_m0[i]; a1 &= ~s_m1[i];
                }
            }
        }
        s_alive[0] = a0; s_alive[1] = a1;
    }
    __syncthreads();

    if (t < n) {
        bool al = (s_alive[t >> 6] >> (t & 63)) & 1ull;
        if (al) {
            u64 fk = ((u64)key32 << 21) | ((u64)(0x7Fu - (u32)c) << 14)
                   | (u64)(0x3FFFu - (u32)anchor);
            int p = atomicAdd(&d_finN[b], 1);
            if (p < FINCAP) d_fin[(size_t)b * FINCAP + p] = fk;
            else d_overflow[b] = 1;
        }
    }
}

// ===== Kernel 3: per-image final top-200 (score desc, cls asc, anchor asc) =====
// Adaptive rounds: entries >= n are zero and can never pass >= tau (> 0), so
// scanning only ceil(n/1024) rounds is exactly equivalent.
__global__ void __launch_bounds__(1024) k_out_fast(float* __restrict__ out) {
    extern __shared__ u64 s_f[];          // FINCAP u64 = 72 KB
    __shared__ u64 buf[512];
    __shared__ int s_cnt, s_n, s_okflag;
    int b = blockIdx.x, t = threadIdx.x;
    int n = min(d_finN[b], FINCAP);
    int R = (n + 1023) >> 10;             // rounds actually containing data

    for (int k = 0; k < R; k++) {
        int i = t + (k << 10);
        s_f[i] = (i < n) ? d_fin[(size_t)b * FINCAP + i] : 0ull;
    }
    if (t < 512) buf[t] = 0ull;
    __syncthreads();

    u32 tau = TAU_MIN;
    int ovf = d_overflow[b];
    if (n > 448) {
        u64 lo = (u64)TAU_MIN + 1, hi = 0xBF800000ull;
        int cntb = n;
        while (lo <= hi) {
            u32 mid = (u32)(lo + ((hi - lo) >> 1));
            if (t == 0) s_cnt = 0;
            __syncthreads();
            int cl = 0;
            for (int k = 0; k < R; k++)
                cl += ((u32)(s_f[t + (k << 10)] >> 21) >= mid);
            #pragma unroll
            for (int o = 16; o; o >>= 1) cl += __shfl_down_sync(0xffffffffu, cl, o);
            if ((t & 31) == 0) atomicAdd(&s_cnt, cl);
            __syncthreads();
            int cn = s_cnt;
            __syncthreads();
            if (cn >= MAXDET) {
                tau = mid; cntb = cn; lo = (u64)mid + 1;
                if (cn <= 448) break;
            } else hi = (u64)mid - 1;
        }
        if (cntb > 448) ovf = 1;
    }

    if (t == 0) s_n = 0;
    __syncthreads();
    for (int k = 0; k < R; k++) {
        u64 v = s_f[t + (k << 10)];
        if (v != 0ull && (u32)(v >> 21) >= tau) {
            int p = atomicAdd(&s_n, 1);
            if (p < 512) buf[p] = v;
        }
    }
    __syncthreads();

    for (int k = 2; k <= 512; k <<= 1) {
        for (int j2 = k >> 1; j2 > 0; j2 >>= 1) {
            if (t < 512) {
                int ixj = t ^ j2;
                if (ixj > t) {
                    u64 x = buf[t], y = buf[ixj];
                    bool sw = ((t & k) == 0) ? (x < y) : (x > y);
                    if (sw) { buf[t] = y; buf[ixj] = x; }
                }
            }
            __syncthreads();
        }
    }

    if (t == 0) {
        u64 v199 = buf[MAXDET - 1];
        u32 s200 = (u32)(v199 >> 21);
        u32 cm = d_capmax[b];
        int ok = (!ovf) && (s200 > cm);
        s_okflag = ok;
        d_ok[b] = ok;
    }
    __syncthreads();

    if (s_okflag && t < MAXDET) {
        u64 v = buf[t];
        float4 bx = make_float4(0.f, 0.f, 0.f, 0.f);
        float so = 0.f, lb = 0.f;
        if (v != 0ull) {
            u32 key32 = (u32)(v >> 21);
            int cls = (int)(0x7Fu - ((u32)(v >> 14) & 0x7Fu));
            int anchor = (int)(0x3FFFu - (u32)(v & 0x3FFF));
            so = __uint_as_float(key32 ^ 0x80000000u);
            bx = d_dboxes[(size_t)b * NA + anchor];
            lb = (float)(cls + 1);
        }
        size_t ob = ((size_t)b * MAXDET + t) * 4;
        out[ob + 0] = bx.x; out[ob + 1] = bx.y;
        out[ob + 2] = bx.z; out[ob + 3] = bx.w;
        out[(size_t)BATCH * MAXDET * 4 + (size_t)b * MAXDET + t] = so;
        out[(size_t)BATCH * MAXDET * 5 + (size_t)b * MAXDET + t] = lb;
    }
}

// ================= FALLBACK (proven R8 path, gated on !d_ok[b]) =============
__global__ void __launch_bounds__(1024) k_probs_fb(const float* __restrict__ logits) {
    int bA = (int)((blockIdx.x * 32) / NA);
    int bB = (int)((blockIdx.x * 32 + 31) / NA);
    if (d_ok[bA] && d_ok[bB]) return;

    __shared__ float s_p[NC][33];
    int w = threadIdx.x >> 5, lane = threadIdx.x & 31;
    long flat = (long)blockIdx.x * 32 + w;
    size_t lbase = (size_t)flat * NCLASS;
    int a0 = (int)(blockIdx.x * 32 - bA * NA);

    float x0 = logits[lbase + lane];
    float x1 = logits[lbase + lane + 32];
    float x2 = (lane < 27) ? logits[lbase + lane + 64] : NEG_INF;

    float m = fmaxf(fmaxf(x0, x1), x2);
    #pragma unroll
    for (int o = 16; o; o >>= 1) m = fmaxf(m, __shfl_down_sync(0xffffffffu, m, o));
    m = __shfl_sync(0xffffffffu, m, 0);

    float e0 = expf(x0 - m), e1 = expf(x1 - m), e2 = expf(x2 - m);
    float s = __fadd_rn(__fadd_rn(e0, e1), e2);
    #pragma unroll
    for (int o = 16; o; o >>= 1) s = __fadd_rn(s, __shfl_down_sync(0xffffffffu, s, o));
    s = __shfl_sync(0xffffffffu, s, 0);

    if (lane >= 1) {
        float p = __fdiv_rn(e0, s);
        s_p[lane - 1][w] = (p > SCORE_T) ? p : NEG_INF;
    }
    {
        float p = __fdiv_rn(e1, s);
        s_p[lane + 31][w] = (p > SCORE_T) ? p : NEG_INF;
    }
    if (lane < 27) {
        float p = __fdiv_rn(e2, s);
        s_p[lane + 63][w] = (p > SCORE_T) ? p : NEG_INF;
    }
    __syncthreads();

    #pragma unroll
    for (int i = threadIdx.x; i < NC * 32; i += 1024) {
        int c = i >> 5, wl = i & 31;
        int a = a0 + wl, b = bA;
        if (a >= NA) { a -= NA; b++; }
        d_probs[((size_t)b * NC + c) * NA + a] = s_p[c][wl];
    }
}

#define TKTHREADS 512
#define TKCAP 512
#define NLOC 18

__global__ void __launch_bounds__(TKTHREADS) k_topk_fb() {
    int b = blockIdx.x / NC, c = blockIdx.x % NC;
    if (d_ok[b]) return;
    const float* sc = &d_probs[((size_t)b * NC + c) * NA];
    int t = threadIdx.x;

    u32 key[NLOC];
    #pragma unroll
    for (int j = 0; j < NLOC; j++) {
        int idx = j * TKTHREADS + t;
        float v = (idx < NA) ? sc[idx] : -1.0f;
        key[j] = (idx < NA && v > SCORE_T) ? fmono(v) : 0u;
    }

    __shared__ int s_cnt;
    u64 lo = 0xBC23D70Bull, hi = 0xBF800000ull;
    u32 tau = 0;
    while (lo <= hi) {
        u32 mid = (u32)(lo + ((hi - lo) >> 1));
        if (t == 0) s_cnt = 0;
        __syncthreads();
        int cl = 0;
        #pragma unroll
        for (int j = 0; j < NLOC; j++) cl += (key[j] >= mid);
        #pragma unroll
        for (int o = 16; o; o >>= 1) cl += __shfl_down_sync(0xffffffffu, cl, o);
        if ((t & 31) == 0) atomicAdd(&s_cnt, cl);
        __syncthreads();
        int cnt = s_cnt;
        __syncthreads();
        if (cnt >= KTOP) { tau = mid; lo = (u64)mid + 1; }
        else             { hi = (u64)mid - 1; }
    }

    __shared__ u64 buf[TKCAP];
    __shared__ int s_n;
    if (t == 0) s_n = 0;
    if (t < TKCAP) buf[t] = 0ull;
    __syncthreads();
    #pragma unroll
    for (int j = 0; j < NLOC; j++) {
        if (key[j] != 0u && key[j] >= tau) {
            int p = atomicAdd(&s_n, 1);
            if (p < TKCAP) {
                u32 anchor = (u32)(j * TKTHREADS + t);
                buf[p] = ((u64)key[j] << 32) | (u64)(0xFFFFFFFFu - anchor);
            }
        }
    }
    __syncthreads();

    for (int k = 2; k <= TKCAP; k <<= 1) {
        for (int j2 = k >> 1; j2 > 0; j2 >>= 1) {
            if (t < TKCAP) {
                int ixj = t ^ j2;
                if (ixj > t) {
                    u64 x = buf[t], y = buf[ixj];
                    bool sw = ((t & k) == 0) ? (x < y) : (x > y);
                    if (sw) { buf[t] = y; buf[ixj] = x; }
                }
            }
            __syncthreads();
        }
    }

    int nv = min(s_n, TKCAP);
    size_t obase = (size_t)b * NCAND + (size_t)c * KTOP;
    float off = __fmul_rn((float)(c + 1), IMGSZ + 1.0f);
    if (t < KTOP) {
        float scv = NEG_INF;
        int anc = 0;
        if (t < nv) {
            u64 v = buf[t];
            u32 h32 = (u32)(v >> 32);
            scv = __uint_as_float(h32 ^ 0x80000000u);
            anc = (int)(0xFFFFFFFFu - (u32)v);
        }
        d_candScore[obase + t]  = scv;
        d_candAnchor[obase + t] = anc;
        float4 raw = d_dboxes[(size_t)b * NA + anc];
        float4 ob;
        ob.x = __fadd_rn(raw.x, off);
        ob.y = __fadd_rn(raw.y, off);
        ob.z = __fadd_rn(raw.z, off);
        ob.w = __fadd_rn(raw.w, off);
        d_candBox[obase + t] = ob;
    }
}

__global__ void __launch_bounds__(416) k_nms_fb() {
    int b = blockIdx.x / NC, c = blockIdx.x % NC;
    if (d_ok[b]) return;
    __shared__ float  s_sc[KTOP];
    __shared__ float4 s_bx[KTOP];
    __shared__ float  s_ar[KTOP];
    __shared__ int    s_alive[KTOP];
    int t = threadIdx.x;
    size_t base = (size_t)b * NCAND + (size_t)c * KTOP;

    float4 my = make_float4(0.f, 0.f, 0.f, 0.f);
    float mya = 0.f;
    if (t < KTOP) {
        float s = d_candScore[base + t];
        float4 bx = d_candBox[base + t];
        s_sc[t] = s;
        s_bx[t] = bx;
        float ar = __fmul_rn(__fsub_rn(bx.z, bx.x), __fsub_rn(bx.w, bx.y));
        s_ar[t] = ar;
        s_alive[t] = isfinite(s) ? 1 : 0;
        my = bx; mya = ar;
    }
    __syncthreads();

    for (int i = 0; i < KTOP; i++) {
        if (s_alive[i]) {
            if (t > i && t < KTOP && s_alive[t]) {
                float4 bi = s_bx[i];
                float lx = fmaxf(bi.x, my.x), ly = fmaxf(bi.y, my.y);
                float rx = fminf(bi.z, my.z), ry = fminf(bi.w, my.w);
                float iw = fmaxf(__fsub_rn(rx, lx), 0.f);
                float ih = fmaxf(__fsub_rn(ry, ly), 0.f);
                float inter = __fmul_rn(iw, ih);
                float den = __fadd_rn(__fsub_rn(__fadd_rn(s_ar[i], mya), inter), 1e-9f);
                float iou = __fdiv_rn(inter, den);
                if (iou > NMS_T) s_alive[t] = 0;
            }
            __syncthreads();
        }
    }
    __syncthreads();
    if (t < KTOP)
        d_candScore[base + t] = s_alive[t] ? s_sc[t] : NEG_INF;
}

#define SELPAD 36864
__global__ void __launch_bounds__(1024) k_select_fb(float* __restrict__ out) {
    int b = blockIdx.x, t = threadIdx.x;
    if (d_ok[b]) return;
    extern __shared__ u32 s_key2[];
    __shared__ u64 buf[512];
    __shared__ int s_cnt, s_n;

    for (int i = t; i < NCAND; i += 1024) {
        float v = d_candScore[(size_t)b * NCAND + i];
        s_key2[i] = isfinite(v) ? fmono(v) : 0u;
    }
    for (int i = NCAND + t; i < SELPAD; i += 1024) s_key2[i] = 0u;
    if (t < 512) buf[t] = 0ull;

    u64 lo = 0xBC23D70Bull, hi = 0xBF800000ull;
    u32 tau = 0;
    const uint4* k4 = (const uint4*)s_key2;
    __syncthreads();
    while (lo <= hi) {
        u32 mid = (u32)(lo + ((hi - lo) >> 1));
        if (t == 0) s_cnt = 0;
        __syncthreads();
        int cl = 0;
        #pragma unroll
        for (int k = 0; k < 9; k++) {
            uint4 v = k4[t + (k << 10)];
            cl += (v.x >= mid) + (v.y >= mid) + (v.z >= mid) + (v.w >= mid);
        }
        #pragma unroll
        for (int o = 16; o; o >>= 1) cl += __shfl_down_sync(0xffffffffu, cl, o);
        if ((t & 31) == 0) atomicAdd(&s_cnt, cl);
        __syncthreads();
        int cnt = s_cnt;
        __syncthreads();
        if (cnt >= MAXDET) { tau = mid; lo = (u64)mid + 1; }
        else               { hi = (u64)mid - 1; }
    }
    if (t == 0) s_n = 0;
    __syncthreads();
    #pragma unroll
    for (int k = 0; k < 36; k++) {
        int i = t + (k << 10);
        if (i < NCAND) {
            u32 kv = s_key2[i];
            if (kv >= tau) {
                int p = atomicAdd(&s_n, 1);
                if (p < 512)
                    buf[p] = ((u64)kv << 32) | (u64)(0xFFFFFFFFu - (u32)i);
            }
        }
    }
    __syncthreads();

    for (int k = 2; k <= 512; k <<= 1) {
        for (int j2 = k >> 1; j2 > 0; j2 >>= 1) {
            if (t < 512) {
                int ixj = t ^ j2;
                if (ixj > t) {
                    u64 x = buf[t], y = buf[ixj];
                    bool sw = ((t & k) == 0) ? (x < y) : (x > y);
                    if (sw) { buf[t] = y; buf[ixj] = x; }
                }
            }
            __syncthreads();
        }
    }

    if (t < MAXDET) {
        u64 v = buf[t];
        u32 h = (u32)(v >> 32);
        float4 bx = make_float4(0.f, 0.f, 0.f, 0.f);
        float so = 0.f, lb = 0.f;
        if (h != 0u) {
            int idx = (int)(0xFFFFFFFFu - (u32)v);
            so = __uint_as_float(h ^ 0x80000000u);
            int cls = idx / KTOP;
            int anc = d_candAnchor[(size_t)b * NCAND + idx];
            bx = d_dboxes[(size_t)b * NA + anc];
            lb = (float)(cls + 1);
        }
        size_t ob = ((size_t)b * MAXDET + t) * 4;
        out[ob + 0] = bx.x; out[ob + 1] = bx.y;
        out[ob + 2] = bx.z; out[ob + 3] = bx.w;
        out[(size_t)BATCH * MAXDET * 4 + (size_t)b * MAXDET + t] = so;
        out[(size_t)BATCH * MAXDET * 5 + (size_t)b * MAXDET + t] = lb;
    }
}

// ================= host =================
extern "C" void kernel_launch(void* const* d_in, const int* in_sizes, int n_in,
                              void* d_out, int out_size) {
    const float* logits  = (const float*)d_in[0];
    const float* reg     = (const float*)d_in[1];
    const float* anchors = (const float*)d_in[2];
    float* out = (float*)d_out;

    k_init<<<3, 1024>>>();
    k_softmax_decode<<<(BATCH * NA) / 32, 1024>>>(logits, reg, anchors);
    k_nms_fast<<<BATCH * NC, 128>>>();
    cudaFuncSetAttribute(k_out_fast, cudaFuncAttributeMaxDynamicSharedMemorySize,
                         FINCAP * (int)sizeof(u64));
    k_out_fast<<<BATCH, 1024, FINCAP * sizeof(u64)>>>(out);
    // fallback chain (no-ops when fast path verified exact)
    k_probs_fb<<<(BATCH * NA) / 32, 1024>>>(logits);
    k_topk_fb<<<BATCH * NC, TKTHREADS>>>();
    k_nms_fb<<<BATCH * NC, 416>>>();
    cudaFuncSetAttribute(k_select_fb, cudaFuncAttributeMaxDynamicSharedMemorySize,
                         SELPAD * (int)sizeof(u32));
    k_select_fb<<<BATCH, 1024, SELPAD * sizeof(u32)>>>(out);
}

// round 16
// speedup vs baseline: 2.2901x; 1.0975x over previous
#include <cuda_runtime.h>

#define BATCH   32
#define NA      8732
#define NCLASS  91
#define NC      90
#define KTOP    400
#define NCAND   (NC * KTOP)      /* 36000 */
#define MAXDET  200
#define IMGSZ   300.0f
#define SCORE_T 0.01f
#define NMS_T   0.45f
#define BBOX_CLIP 4.135166556742356f
#define NEG_INF __int_as_float(0xff800000)
#define TAU_MIN 0xBC23D70Cu      /* fmono(0.01f)+1 */
#define T0      0.15f            /* fixed emission threshold (verified safe) */
#define BCAP    128              /* bucket capacity per (b,c) */
#define FINCAP  9216
#define OUTCAP  1024

typedef unsigned long long u64;
typedef unsigned u32;

// -------- scratch (device globals; zero-init; self-resetting protocol) -----
__device__ float  d_probs[(size_t)BATCH * NC * NA];      // fallback only
__device__ float4 d_dboxes[(size_t)BATCH * NA];
// fast path
__device__ u64 d_selKey[(size_t)BATCH * NC * BCAP];
__device__ int d_selN[BATCH * NC];        // reset by k_nms_fast
__device__ int d_overflow[BATCH];         // reset by k_out_fast
__device__ u64 d_fin[(size_t)BATCH * FINCAP];
__device__ int d_finN[BATCH];             // reset by k_out_fast
__device__ int d_ok[BATCH];               // overwritten every run
// fallback path
__device__ float  d_candScore[(size_t)BATCH * NCAND];
__device__ int    d_candAnchor[(size_t)BATCH * NCAND];

__device__ __forceinline__ u32 fmono(float f) {
    u32 u = __float_as_uint(f);
    return u ^ ((u >> 31) ? 0xFFFFFFFFu : 0x80000000u);
}
#define CAPMAX (fmono(T0) + 16)   /* excluded p <= T0*(1+2^-22) < this */

// ================= Kernel 1: softmax (XLA:GPU warp order) + decode + emit ===
// FROZEN FP ARITHMETIC: max/exp/sum trees and __fdiv_rn scores bitwise-match
// the reference lowering. Emission set {e > RN(s*T0)} is score-downward-closed;
// exactness is verified downstream (CAPMAX / s200 / overflow -> fallback).
__global__ void __launch_bounds__(1024) k_softmax_decode(
        const float* __restrict__ logits,
        const float* __restrict__ reg,
        const float* __restrict__ anchors) {
    int w = threadIdx.x >> 5, lane = threadIdx.x & 31;
    long flat = (long)blockIdx.x * 32 + w;
    size_t lbase = (size_t)flat * NCLASS;
    int b0 = (int)((blockIdx.x * 32) / NA);
    int a0 = (int)(blockIdx.x * 32 - b0 * NA);
    int aw = a0 + w, bw = b0;
    if (aw >= NA) { aw -= NA; bw++; }

    float x0 = logits[lbase + lane];
    float x1 = logits[lbase + lane + 32];
    float x2 = (lane < 27) ? logits[lbase + lane + 64] : NEG_INF;

    float m = fmaxf(fmaxf(x0, x1), x2);
    #pragma unroll
    for (int o = 16; o; o >>= 1) m = fmaxf(m, __shfl_down_sync(0xffffffffu, m, o));
    m = __shfl_sync(0xffffffffu, m, 0);

    float e0 = expf(x0 - m), e1 = expf(x1 - m), e2 = expf(x2 - m);
    float s = __fadd_rn(__fadd_rn(e0, e1), e2);
    #pragma unroll
    for (int o = 16; o; o >>= 1) s = __fadd_rn(s, __shfl_down_sync(0xffffffffu, s, o));
    s = __shfl_sync(0xffffffffu, s, 0);

    float thr = __fmul_rn(s, T0);
    #pragma unroll
    for (int r = 0; r < 3; r++) {
        float e = (r == 0) ? e0 : (r == 1) ? e1 : e2;
        int c  = (r == 0) ? lane - 1 : (r == 1) ? lane + 31 : lane + 63;
        bool valid = (r == 0) ? (lane >= 1) : (r == 1) ? true : (lane < 27);
        if (valid && e > thr) {
            float p = __fdiv_rn(e, s);               // frozen exact score
            u64 key = ((u64)fmono(p) << 14) | (u64)(0x3FFFu - (u32)aw);
            int bc = bw * NC + c;
            int idx = atomicAdd(&d_selN[bc], 1);
            if (idx < BCAP) d_selKey[(size_t)bc * BCAP + idx] = key;
            else d_overflow[bw] = 1;
        }
    }

    if (threadIdx.x < 32) {
        int a = a0 + threadIdx.x, b = b0;
        if (a >= NA) { a -= NA; b++; }
        long fl = (long)blockIdx.x * 32 + threadIdx.x;
        float4 rg = ((const float4*)reg)[fl];
        float4 an = ((const float4*)anchors)[a];
        float wa = __fsub_rn(an.z, an.x), ha = __fsub_rn(an.w, an.y);
        float cxa = __fadd_rn(an.x, __fmul_rn(0.5f, wa));
        float cya = __fadd_rn(an.y, __fmul_rn(0.5f, ha));
        float dx = __fdiv_rn(rg.x, 10.0f), dy = __fdiv_rn(rg.y, 10.0f);
        float dw = fminf(__fdiv_rn(rg.z, 5.0f), BBOX_CLIP);
        float dh = fminf(__fdiv_rn(rg.w, 5.0f), BBOX_CLIP);
        float cx = __fadd_rn(__fmul_rn(dx, wa), cxa);
        float cy = __fadd_rn(__fmul_rn(dy, ha), cya);
        float bwd = __fmul_rn(expf(dw), wa), bhd = __fmul_rn(expf(dh), ha);
        float hw = __fmul_rn(0.5f, bwd), hh = __fmul_rn(0.5f, bhd);
        float4 bx;
        bx.x = fminf(fmaxf(__fsub_rn(cx, hw), 0.f), IMGSZ);
        bx.y = fminf(fmaxf(__fsub_rn(cy, hh), 0.f), IMGSZ);
        bx.z = fminf(fmaxf(__fadd_rn(cx, hw), 0.f), IMGSZ);
        bx.w = fminf(fmaxf(__fadd_rn(cy, hh), 0.f), IMGSZ);
        d_dboxes[(size_t)b * NA + a] = bx;
    }
}

// ---- warp-register bitonic helper ----
__device__ __forceinline__ u64 ce_shfl(u64 x, int j2, bool dird, int lane) {
    u64 y = __shfl_xor_sync(0xffffffffu, x, j2);
    bool lower = (lane & j2) == 0;
    bool keepmax = (dird == lower);
    u64 mx = (x > y) ? x : y;
    u64 mn = (x > y) ? y : x;
    return keepmax ? mx : mn;
}

// ===== Kernel 2: per-(b,c) warp-sort<=128 + greedy NMS + emit survivors =====
__global__ void __launch_bounds__(128) k_nms_fast() {
    int bc = blockIdx.x;
    int b = bc / NC, c = bc % NC;
    int n = min(d_selN[bc], BCAP);
    if (n == 0) return;
    int t = threadIdx.x;
    if (t == 0) d_selN[bc] = 0;           // self-reset for next replay

    __shared__ u64   s_key[128];
    __shared__ float4 s_bx[BCAP];
    __shared__ float  s_ar[BCAP];
    __shared__ u64   s_m0[BCAP], s_m1[BCAP];
    __shared__ u64   s_alive[2], s_hk[2];

    if (t < 2) { s_alive[t] = 0ull; s_hk[t] = 0ull; }

    if (t < 32) {
        int lane = t;
        u64 v[4];
        #pragma unroll
        for (int r = 0; r < 4; r++) {
            int i = r * 32 + lane;
            v[r] = (i < n) ? d_selKey[(size_t)bc * BCAP + i] : 0ull;
        }
        #pragma unroll
        for (int k = 2; k <= 128; k <<= 1) {
            #pragma unroll
            for (int j2 = 64; j2 >= 1; j2 >>= 1) {
                if (j2 > (k >> 1)) continue;
                if (j2 >= 32) {
                    int rstep = j2 >> 5;
                    #pragma unroll
                    for (int r = 0; r < 4; r++) {
                        if ((r & rstep) == 0) {
                            int i = r * 32 + lane;
                            bool dird = ((i & k) == 0);
                            u64 lo2 = v[r], hi2 = v[r + rstep];
                            bool sw = dird ? (lo2 < hi2) : (lo2 > hi2);
                            if (sw) { v[r] = hi2; v[r + rstep] = lo2; }
                        }
                    }
                } else {
                    #pragma unroll
                    for (int r = 0; r < 4; r++) {
                        int i = r * 32 + lane;
                        bool dird = ((i & k) == 0);
                        v[r] = ce_shfl(v[r], j2, dird, lane);
                    }
                }
            }
        }
        #pragma unroll
        for (int r = 0; r < 4; r++) s_key[r * 32 + lane] = v[r];
    }
    __syncthreads();

    u64 v = s_key[t];
    u32 key32 = (u32)(v >> 14);
    int anchor = (int)(0x3FFFu - (u32)(v & 0x3FFF));
    float off = __fmul_rn((float)(c + 1), IMGSZ + 1.0f);
    if (t < n) {
        float4 raw = d_dboxes[(size_t)b * NA + anchor];
        float4 bx;
        bx.x = __fadd_rn(raw.x, off);
        bx.y = __fadd_rn(raw.y, off);
        bx.z = __fadd_rn(raw.z, off);
        bx.w = __fadd_rn(raw.w, off);
        s_bx[t] = bx;
        s_ar[t] = __fmul_rn(__fsub_rn(bx.z, bx.x), __fsub_rn(bx.w, bx.y));
        atomicOr(&s_alive[t >> 6], 1ull << (t & 63));
    }
    __syncthreads();

    if (t < n) {
        float4 bi = s_bx[t];
        float ai = s_ar[t];
        u64 m0 = 0ull, m1 = 0ull;
        for (int j = t + 1; j < n; j++) {
            float4 bj = s_bx[j];
            float lx = fmaxf(bi.x, bj.x), ly = fmaxf(bi.y, bj.y);
            float rx = fminf(bi.z, bj.z), ry = fminf(bi.w, bj.w);
            float iw = fmaxf(__fsub_rn(rx, lx), 0.f);
            float ih = fmaxf(__fsub_rn(ry, ly), 0.f);
            float inter = __fmul_rn(iw, ih);
            bool kill = false;
            if (inter > 0.f) {
                float den = __fadd_rn(__fsub_rn(__fadd_rn(ai, s_ar[j]), inter), 1e-9f);
                kill = (__fdiv_rn(inter, den) > NMS_T);
            }
            if (j < 64) m0 |= ((u64)kill) << j;
            else        m1 |= ((u64)kill) << (j - 64);
        }
        s_m0[t] = m0; s_m1[t] = m1;
        if (m0 | m1) atomicOr(&s_hk[t >> 6], 1ull << (t & 63));
    }
    __syncthreads();

    if (t == 0) {
        u64 a0 = s_alive[0], a1 = s_alive[1];
        #pragma unroll
        for (int w = 0; w < 2; w++) {
            u64 rem = s_hk[w];
            while (rem) {
                int bit = __ffsll((long long)rem) - 1;
                rem &= rem - 1;
                u64 ab = (w == 0) ? a0 : a1;
                if ((ab >> bit) & 1ull) {
                    int i = (w << 6) + bit;
                    a0 &= ~s_m0[i]; a1 &= ~s_m1[i];
                }
            }
        }
        s_alive[0] = a0; s_alive[1] = a1;
    }
    __syncthreads();

    if (t < n) {
        bool al = (s_alive[t >> 6] >> (t & 63)) & 1ull;
        if (al) {
            u64 fk = ((u64)key32 << 21) | ((u64)(0x7Fu - (u32)c) << 14)
                   | (u64)(0x3FFFu - (u32)anchor);
            int p = atomicAdd(&d_finN[b], 1);
            if (p < FINCAP) d_fin[(size_t)b * FINCAP + p] = fk;
            else d_overflow[b] = 1;
        }
    }
}

// ===== Kernel 3: per-image final top-200 (score desc, cls asc, anchor asc) =====
// Threshold search only when n > 960; zero keys never pass (tau >= TAU_MIN > 0).
__global__ void __launch_bounds__(1024) k_out_fast(float* __restrict__ out) {
    extern __shared__ u64 s_f[];          // FINCAP u64 = 72 KB
    __shared__ u64 buf[OUTCAP];
    __shared__ int s_cnt, s_n, s_okflag;
    int b = blockIdx.x, t = threadIdx.x;
    int n = min(d_finN[b], FINCAP);
    int R = (n + 1023) >> 10;

    for (int k = 0; k < R; k++) {
        int i = t + (k << 10);
        s_f[i] = (i < n) ? d_fin[(size_t)b * FINCAP + i] : 0ull;
    }
    buf[t] = 0ull;
    __syncthreads();

    u32 tau = TAU_MIN;
    int ovf = d_overflow[b];
    if (n > OUTCAP - 64) {
        u64 lo = (u64)TAU_MIN + 1, hi = 0xBF800000ull;
        int cntb = n;
        while (lo <= hi) {
            u32 mid = (u32)(lo + ((hi - lo) >> 1));
            if (t == 0) s_cnt = 0;
            __syncthreads();
            int cl = 0;
            for (int k = 0; k < R; k++)
                cl += ((u32)(s_f[t + (k << 10)] >> 21) >= mid);
            #pragma unroll
            for (int o = 16; o; o >>= 1) cl += __shfl_down_sync(0xffffffffu, cl, o);
            if ((t & 31) == 0) atomicAdd(&s_cnt, cl);
            __syncthreads();
            int cn = s_cnt;
            __syncthreads();
            if (cn >= MAXDET) {
                tau = mid; cntb = cn; lo = (u64)mid + 1;
                if (cn <= OUTCAP - 64) break;
            } else hi = (u64)mid - 1;
        }
        if (cntb > OUTCAP - 64) ovf = 1;
    }

    if (t == 0) s_n = 0;
    __syncthreads();
    for (int k = 0; k < R; k++) {
        u64 v = s_f[t + (k << 10)];
        if (v != 0ull && (u32)(v >> 21) >= tau) {
            int p = atomicAdd(&s_n, 1);
            if (p < OUTCAP) buf[p] = v;
        }
    }
    __syncthreads();

    for (int k = 2; k <= OUTCAP; k <<= 1) {
        for (int j2 = k >> 1; j2 > 0; j2 >>= 1) {
            int ixj = t ^ j2;
            if (ixj > t) {
                u64 x = buf[t], y = buf[ixj];
                bool sw = ((t & k) == 0) ? (x < y) : (x > y);
                if (sw) { buf[t] = y; buf[ixj] = x; }
            }
            __syncthreads();
        }
    }

    if (t == 0) {
        u64 v199 = buf[MAXDET - 1];
        u32 s200 = (u32)(v199 >> 21);
        int ok = (!ovf) && (s200 > CAPMAX);
        s_okflag = ok;
        d_ok[b] = ok;
        d_finN[b] = 0;                    // self-reset for next replay
        d_overflow[b] = 0;
    }
    __syncthreads();

    if (s_okflag && t < MAXDET) {
        u64 v = buf[t];
        float4 bx = make_float4(0.f, 0.f, 0.f, 0.f);
        float so = 0.f, lb = 0.f;
        if (v != 0ull) {
            u32 key32 = (u32)(v >> 21);
            int cls = (int)(0x7Fu - ((u32)(v >> 14) & 0x7Fu));
            int anchor = (int)(0x3FFFu - (u32)(v & 0x3FFF));
            so = __uint_as_float(key32 ^ 0x80000000u);
            bx = d_dboxes[(size_t)b * NA + anchor];
            lb = (float)(cls + 1);
        }
        size_t ob = ((size_t)b * MAXDET + t) * 4;
        out[ob + 0] = bx.x; out[ob + 1] = bx.y;
        out[ob + 2] = bx.z; out[ob + 3] = bx.w;
        out[(size_t)BATCH * MAXDET * 4 + (size_t)b * MAXDET + t] = so;
        out[(size_t)BATCH * MAXDET * 5 + (size_t)b * MAXDET + t] = lb;
    }
}

// ================= FALLBACK (proven R8 path, gated on !d_ok[b]) =============
__global__ void __launch_bounds__(1024) k_probs_fb(const float* __restrict__ logits) {
    int bA = (int)((blockIdx.x * 32) / NA);
    int bB = (int)((blockIdx.x * 32 + 31) / NA);
    if (d_ok[bA] && d_ok[bB]) return;

    __shared__ float s_p[NC][33];
    int w = threadIdx.x >> 5, lane = threadIdx.x & 31;
    long flat = (long)blockIdx.x * 32 + w;
    size_t lbase = (size_t)flat * NCLASS;
    int a0 = (int)(blockIdx.x * 32 - bA * NA);

    float x0 = logits[lbase + lane];
    float x1 = logits[lbase + lane + 32];
    float x2 = (lane < 27) ? logits[lbase + lane + 64] : NEG_INF;

    float m = fmaxf(fmaxf(x0, x1), x2);
    #pragma unroll
    for (int o = 16; o; o >>= 1) m = fmaxf(m, __shfl_down_sync(0xffffffffu, m, o));
    m = __shfl_sync(0xffffffffu, m, 0);

    float e0 = expf(x0 - m), e1 = expf(x1 - m), e2 = expf(x2 - m);
    float s = __fadd_rn(__fadd_rn(e0, e1), e2);
    #pragma unroll
    for (int o = 16; o; o >>= 1) s = __fadd_rn(s, __shfl_down_sync(0xffffffffu, s, o));
    s = __shfl_sync(0xffffffffu, s, 0);

    if (lane >= 1) {
        float p = __fdiv_rn(e0, s);
        s_p[lane - 1][w] = (p > SCORE_T) ? p : NEG_INF;
    }
    {
        float p = __fdiv_rn(e1, s);
        s_p[lane + 31][w] = (p > SCORE_T) ? p : NEG_INF;
    }
    if (lane < 27) {
        float p = __fdiv_rn(e2, s);
        s_p[lane + 63][w] = (p > SCORE_T) ? p : NEG_INF;
    }
    __syncthreads();

    #pragma unroll
    for (int i = threadIdx.x; i < NC * 32; i += 1024) {
        int c = i >> 5, wl = i & 31;
        int a = a0 + wl, b = bA;
        if (a >= NA) { a -= NA; b++; }
        d_probs[((size_t)b * NC + c) * NA + a] = s_p[c][wl];
    }
}

#define TKTHREADS 512
#define TKCAP 512
#define NLOC 18

// merged fallback: per-(b,c) top-400 + serial greedy NMS in one block
__global__ void __launch_bounds__(TKTHREADS) k_topknms_fb() {
    int b = blockIdx.x / NC, c = blockIdx.x % NC;
    if (d_ok[b]) return;
    const float* sc = &d_probs[((size_t)b * NC + c) * NA];
    int t = threadIdx.x;

    u32 key[NLOC];
    #pragma unroll
    for (int j = 0; j < NLOC; j++) {
        int idx = j * TKTHREADS + t;
        float v = (idx < NA) ? sc[idx] : -1.0f;
        key[j] = (idx < NA && v > SCORE_T) ? fmono(v) : 0u;
    }

    __shared__ int s_cnt;
    u64 lo = 0xBC23D70Bull, hi = 0xBF800000ull;
    u32 tau = 0;
    while (lo <= hi) {
        u32 mid = (u32)(lo + ((hi - lo) >> 1));
        if (t == 0) s_cnt = 0;
        __syncthreads();
        int cl = 0;
        #pragma unroll
        for (int j = 0; j < NLOC; j++) cl += (key[j] >= mid);
        #pragma unroll
        for (int o = 16; o; o >>= 1) cl += __shfl_down_sync(0xffffffffu, cl, o);
        if ((t & 31) == 0) atomicAdd(&s_cnt, cl);
        __syncthreads();
        int cnt = s_cnt;
        __syncthreads();
        if (cnt >= KTOP) { tau = mid; lo = (u64)mid + 1; }
        else             { hi = (u64)mid - 1; }
    }

    __shared__ u64 buf[TKCAP];
    __shared__ int s_n;
    if (t == 0) s_n = 0;
    buf[t] = 0ull;
    __syncthreads();
    #pragma unroll
    for (int j = 0; j < NLOC; j++) {
        if (key[j] != 0u && key[j] >= tau) {
            int p = atomicAdd(&s_n, 1);
            if (p < TKCAP) {
                u32 anchor = (u32)(j * TKTHREADS + t);
                buf[p] = ((u64)key[j] << 32) | (u64)(0xFFFFFFFFu - anchor);
            }
        }
    }
    __syncthreads();

    for (int k = 2; k <= TKCAP; k <<= 1) {
        for (int j2 = k >> 1; j2 > 0; j2 >>= 1) {
            int ixj = t ^ j2;
            if (ixj > t) {
                u64 x = buf[t], y = buf[ixj];
                bool sw = ((t & k) == 0) ? (x < y) : (x > y);
                if (sw) { buf[t] = y; buf[ixj] = x; }
            }
            __syncthreads();
        }
    }

    // ---- phase 2: serial greedy NMS on the sorted top-400 ----
    __shared__ float  s_sc[KTOP];
    __shared__ float4 s_bx[KTOP];
    __shared__ float  s_ar[KTOP];
    __shared__ int    s_alive[KTOP];
    int nv = min(s_n, TKCAP);
    float off = __fmul_rn((float)(c + 1), IMGSZ + 1.0f);

    float4 my = make_float4(0.f, 0.f, 0.f, 0.f);
    float mya = 0.f;
    int myanc = 0;
    if (t < KTOP) {
        float scv = NEG_INF;
        int anc = 0;
        if (t < nv) {
            u64 v = buf[t];
            u32 h32 = (u32)(v >> 32);
            scv = __uint_as_float(h32 ^ 0x80000000u);
            anc = (int)(0xFFFFFFFFu - (u32)v);
        }
        myanc = anc;
        float4 raw = d_dboxes[(size_t)b * NA + anc];
        float4 bx;
        bx.x = __fadd_rn(raw.x, off);
        bx.y = __fadd_rn(raw.y, off);
        bx.z = __fadd_rn(raw.z, off);
        bx.w = __fadd_rn(raw.w, off);
        s_sc[t] = scv;
        s_bx[t] = bx;
        float ar = __fmul_rn(__fsub_rn(bx.z, bx.x), __fsub_rn(bx.w, bx.y));
        s_ar[t] = ar;
        s_alive[t] = isfinite(scv) ? 1 : 0;
        my = bx; mya = ar;
    }
    __syncthreads();

    for (int i = 0; i < KTOP; i++) {
        if (s_alive[i]) {
            if (t > i && t < KTOP && s_alive[t]) {
                float4 bi = s_bx[i];
                float lx = fmaxf(bi.x, my.x), ly = fmaxf(bi.y, my.y);
                float rx = fminf(bi.z, my.z), ry = fminf(bi.w, my.w);
                float iw = fmaxf(__fsub_rn(rx, lx), 0.f);
                float ih = fmaxf(__fsub_rn(ry, ly), 0.f);
                float inter = __fmul_rn(iw, ih);
                float den = __fadd_rn(__fsub_rn(__fadd_rn(s_ar[i], mya), inter), 1e-9f);
                float iou = __fdiv_rn(inter, den);
                if (iou > NMS_T) s_alive[t] = 0;
            }
            __syncthreads();
        }
    }
    __syncthreads();
    if (t < KTOP) {
        size_t obase = (size_t)b * NCAND + (size_t)c * KTOP;
        d_candScore[obase + t]  = s_alive[t] ? s_sc[t] : NEG_INF;
        d_candAnchor[obase + t] = myanc;
    }
}

#define SELPAD 36864
__global__ void __launch_bounds__(1024) k_select_fb(float* __restrict__ out) {
    int b = blockIdx.x, t = threadIdx.x;
    if (d_ok[b]) return;
    extern __shared__ u32 s_key2[];
    __shared__ u64 buf[512];
    __shared__ int s_cnt, s_n;

    for (int i = t; i < NCAND; i += 1024) {
        float v = d_candScore[(size_t)b * NCAND + i];
        s_key2[i] = isfinite(v) ? fmono(v) : 0u;
    }
    for (int i = NCAND + t; i < SELPAD; i += 1024) s_key2[i] = 0u;
    if (t < 512) buf[t] = 0ull;

    u64 lo = 0xBC23D70Bull, hi = 0xBF800000ull;
    u32 tau = 0;
    const uint4* k4 = (const uint4*)s_key2;
    __syncthreads();
    while (lo <= hi) {
        u32 mid = (u32)(lo + ((hi - lo) >> 1));
        if (t == 0) s_cnt = 0;
        __syncthreads();
        int cl = 0;
        #pragma unroll
        for (int k = 0; k < 9; k++) {
            uint4 v = k4[t + (k << 10)];
            cl += (v.x >= mid) + (v.y >= mid) + (v.z >= mid) + (v.w >= mid);
        }
        #pragma unroll
        for (int o = 16; o; o >>= 1) cl += __shfl_down_sync(0xffffffffu, cl, o);
        if ((t & 31) == 0) atomicAdd(&s_cnt, cl);
        __syncthreads();
        int cnt = s_cnt;
        __syncthreads();
        if (cnt >= MAXDET) { tau = mid; lo = (u64)mid + 1; }
        else               { hi = (u64)mid - 1; }
    }
    if (t == 0) s_n = 0;
    __syncthreads();
    #pragma unroll
    for (int k = 0; k < 36; k++) {
        int i = t + (k << 10);
        if (i < NCAND) {
            u32 kv = s_key2[i];
            if (kv >= tau) {
                int p = atomicAdd(&s_n, 1);
                if (p < 512)
                    buf[p] = ((u64)kv << 32) | (u64)(0xFFFFFFFFu - (u32)i);
            }
        }
    }
    __syncthreads();

    for (int k = 2; k <= 512; k <<= 1) {
        for (int j2 = k >> 1; j2 > 0; j2 >>= 1) {
            if (t < 512) {
                int ixj = t ^ j2;
                if (ixj > t) {
                    u64 x = buf[t], y = buf[ixj];
                    bool sw = ((t & k) == 0) ? (x < y) : (x > y);
                    if (sw) { buf[t] = y; buf[ixj] = x; }
                }
            }
            __syncthreads();
        }
    }

    if (t < MAXDET) {
        u64 v = buf[t];
        u32 h = (u32)(v >> 32);
        float4 bx = make_float4(0.f, 0.f, 0.f, 0.f);
        float so = 0.f, lb = 0.f;
        if (h != 0u) {
            int idx = (int)(0xFFFFFFFFu - (u32)v);
            so = __uint_as_float(h ^ 0x80000000u);
            int cls = idx / KTOP;
            int anc = d_candAnchor[(size_t)b * NCAND + idx];
            bx = d_dboxes[(size_t)b * NA + anc];
            lb = (float)(cls + 1);
        }
        size_t ob = ((size_t)b * MAXDET + t) * 4;
        out[ob + 0] = bx.x; out[ob + 1] = bx.y;
        out[ob + 2] = bx.z; out[ob + 3] = bx.w;
        out[(size_t)BATCH * MAXDET * 4 + (size_t)b * MAXDET + t] = so;
        out[(size_t)BATCH * MAXDET * 5 + (size_t)b * MAXDET + t] = lb;
    }
}

// ================= host =================
extern "C" void kernel_launch(void* const* d_in, const int* in_sizes, int n_in,
                              void* d_out, int out_size) {
    const float* logits  = (const float*)d_in[0];
    const float* reg     = (const float*)d_in[1];
    const float* anchors = (const float*)d_in[2];
    float* out = (float*)d_out;

    k_softmax_decode<<<(BATCH * NA) / 32, 1024>>>(logits, reg, anchors);
    k_nms_fast<<<BATCH * NC, 128>>>();
    cudaFuncSetAttribute(k_out_fast, cudaFuncAttributeMaxDynamicSharedMemorySize,
                         FINCAP * (int)sizeof(u64));
    k_out_fast<<<BATCH, 1024, FINCAP * sizeof(u64)>>>(out);
    // fallback chain (no-ops when fast path verified exact)
    k_probs_fb<<<(BATCH * NA) / 32, 1024>>>(logits);
    k_topknms_fb<<<BATCH * NC, TKTHREADS>>>();
    cudaFuncSetAttribute(k_select_fb, cudaFuncAttributeMaxDynamicSharedMemorySize,
                         SELPAD * (int)sizeof(u32));
    k_select_fb<<<BATCH, 1024, SELPAD * sizeof(u32)>>>(out);
}

// round 17
// speedup vs baseline: 2.3260x; 1.0157x over previous
#include <cuda_runtime.h>

#define BATCH   32
#define NA      8732
#define NCLASS  91
#define NC      90
#define KTOP    400
#define NCAND   (NC * KTOP)      /* 36000 */
#define MAXDET  200
#define IMGSZ   300.0f
#define SCORE_T 0.01f
#define NMS_T   0.45f
#define BBOX_CLIP 4.135166556742356f
#define NEG_INF __int_as_float(0xff800000)
#define TAU_MIN 0xBC23D70Cu      /* fmono(0.01f)+1 */
#define T0      0.15f            /* fixed emission threshold (verified safe) */
#define BCAP    128              /* bucket capacity per (b,c) */
#define FINCAP  9216
#define OUTCAP  1024

typedef unsigned long long u64;
typedef unsigned u32;

// -------- scratch (device globals; zero-init; self-resetting protocol) -----
__device__ float  d_probs[(size_t)BATCH * NC * NA];      // fallback only
__device__ float4 d_dboxes[(size_t)BATCH * NA];
// fast path
__device__ u64 d_selKey[(size_t)BATCH * NC * BCAP];
__device__ int d_selN[BATCH * NC];        // reset by k_nms_fast
__device__ int d_overflow[BATCH];         // reset by k_out_fast
__device__ u64 d_fin[(size_t)BATCH * FINCAP];
__device__ int d_finN[BATCH];             // reset by k_out_fast
__device__ int d_ok[BATCH];               // overwritten every run
// fallback path
__device__ float  d_candScore[(size_t)BATCH * NCAND];
__device__ int    d_candAnchor[(size_t)BATCH * NCAND];

__device__ __forceinline__ u32 fmono(float f) {
    u32 u = __float_as_uint(f);
    return u ^ ((u >> 31) ? 0xFFFFFFFFu : 0x80000000u);
}
#define CAPMAX (fmono(T0) + 16)   /* excluded p <= T0*(1+2^-22) < this */

// ================= Kernel 1: softmax (XLA:GPU warp order) + decode + emit ===
// FROZEN FP ARITHMETIC: max/exp/sum trees and __fdiv_rn scores bitwise-match
// the reference lowering. Emission set {e > RN(s*T0)} is score-downward-closed;
// exactness is verified downstream (CAPMAX / s200 / overflow -> fallback).
__global__ void __launch_bounds__(1024) k_softmax_decode(
        const float* __restrict__ logits,
        const float* __restrict__ reg,
        const float* __restrict__ anchors) {
    int w = threadIdx.x >> 5, lane = threadIdx.x & 31;
    long flat = (long)blockIdx.x * 32 + w;
    size_t lbase = (size_t)flat * NCLASS;
    int b0 = (int)((blockIdx.x * 32) / NA);
    int a0 = (int)(blockIdx.x * 32 - b0 * NA);
    int aw = a0 + w, bw = b0;
    if (aw >= NA) { aw -= NA; bw++; }

    float x0 = logits[lbase + lane];
    float x1 = logits[lbase + lane + 32];
    float x2 = (lane < 27) ? logits[lbase + lane + 64] : NEG_INF;

    float m = fmaxf(fmaxf(x0, x1), x2);
    #pragma unroll
    for (int o = 16; o; o >>= 1) m = fmaxf(m, __shfl_down_sync(0xffffffffu, m, o));
    m = __shfl_sync(0xffffffffu, m, 0);

    float e0 = expf(x0 - m), e1 = expf(x1 - m), e2 = expf(x2 - m);
    float s = __fadd_rn(__fadd_rn(e0, e1), e2);
    #pragma unroll
    for (int o = 16; o; o >>= 1) s = __fadd_rn(s, __shfl_down_sync(0xffffffffu, s, o));
    s = __shfl_sync(0xffffffffu, s, 0);

    float thr = __fmul_rn(s, T0);
    #pragma unroll
    for (int r = 0; r < 3; r++) {
        float e = (r == 0) ? e0 : (r == 1) ? e1 : e2;
        int c  = (r == 0) ? lane - 1 : (r == 1) ? lane + 31 : lane + 63;
        bool valid = (r == 0) ? (lane >= 1) : (r == 1) ? true : (lane < 27);
        if (valid && e > thr) {
            float p = __fdiv_rn(e, s);               // frozen exact score
            u64 key = ((u64)fmono(p) << 14) | (u64)(0x3FFFu - (u32)aw);
            int bc = bw * NC + c;
            int idx = atomicAdd(&d_selN[bc], 1);
            if (idx < BCAP) d_selKey[(size_t)bc * BCAP + idx] = key;
            else d_overflow[bw] = 1;
        }
    }

    if (threadIdx.x < 32) {
        int a = a0 + threadIdx.x, b = b0;
        if (a >= NA) { a -= NA; b++; }
        long fl = (long)blockIdx.x * 32 + threadIdx.x;
        float4 rg = ((const float4*)reg)[fl];
        float4 an = ((const float4*)anchors)[a];
        float wa = __fsub_rn(an.z, an.x), ha = __fsub_rn(an.w, an.y);
        float cxa = __fadd_rn(an.x, __fmul_rn(0.5f, wa));
        float cya = __fadd_rn(an.y, __fmul_rn(0.5f, ha));
        float dx = __fdiv_rn(rg.x, 10.0f), dy = __fdiv_rn(rg.y, 10.0f);
        float dw = fminf(__fdiv_rn(rg.z, 5.0f), BBOX_CLIP);
        float dh = fminf(__fdiv_rn(rg.w, 5.0f), BBOX_CLIP);
        float cx = __fadd_rn(__fmul_rn(dx, wa), cxa);
        float cy = __fadd_rn(__fmul_rn(dy, ha), cya);
        float bwd = __fmul_rn(expf(dw), wa), bhd = __fmul_rn(expf(dh), ha);
        float hw = __fmul_rn(0.5f, bwd), hh = __fmul_rn(0.5f, bhd);
        float4 bx;
        bx.x = fminf(fmaxf(__fsub_rn(cx, hw), 0.f), IMGSZ);
        bx.y = fminf(fmaxf(__fsub_rn(cy, hh), 0.f), IMGSZ);
        bx.z = fminf(fmaxf(__fadd_rn(cx, hw), 0.f), IMGSZ);
        bx.w = fminf(fmaxf(__fadd_rn(cy, hh), 0.f), IMGSZ);
        d_dboxes[(size_t)b * NA + a] = bx;
    }
}

// ---- warp-register bitonic helper ----
__device__ __forceinline__ u64 ce_shfl(u64 x, int j2, bool dird, int lane) {
    u64 y = __shfl_xor_sync(0xffffffffu, x, j2);
    bool lower = (lane & j2) == 0;
    bool keepmax = (dird == lower);
    u64 mx = (x > y) ? x : y;
    u64 mn = (x > y) ? y : x;
    return keepmax ? mx : mn;
}

// ===== Kernel 2: per-(b,c) warp-sort<=128 + greedy NMS + emit survivors =====
__global__ void __launch_bounds__(128) k_nms_fast() {
    int bc = blockIdx.x;
    int b = bc / NC, c = bc % NC;
    int n = min(d_selN[bc], BCAP);
    if (n == 0) return;
    int t = threadIdx.x;
    if (t == 0) d_selN[bc] = 0;           // self-reset for next replay

    __shared__ u64   s_key[128];
    __shared__ float4 s_bx[BCAP];
    __shared__ float  s_ar[BCAP];
    __shared__ u64   s_m0[BCAP], s_m1[BCAP];
    __shared__ u64   s_alive[2], s_hk[2];

    if (t < 2) { s_alive[t] = 0ull; s_hk[t] = 0ull; }

    if (t < 32) {
        int lane = t;
        u64 v[4];
        #pragma unroll
        for (int r = 0; r < 4; r++) {
            int i = r * 32 + lane;
            v[r] = (i < n) ? d_selKey[(size_t)bc * BCAP + i] : 0ull;
        }
        #pragma unroll
        for (int k = 2; k <= 128; k <<= 1) {
            #pragma unroll
            for (int j2 = 64; j2 >= 1; j2 >>= 1) {
                if (j2 > (k >> 1)) continue;
                if (j2 >= 32) {
                    int rstep = j2 >> 5;
                    #pragma unroll
                    for (int r = 0; r < 4; r++) {
                        if ((r & rstep) == 0) {
                            int i = r * 32 + lane;
                            bool dird = ((i & k) == 0);
                            u64 lo2 = v[r], hi2 = v[r + rstep];
                            bool sw = dird ? (lo2 < hi2) : (lo2 > hi2);
                            if (sw) { v[r] = hi2; v[r + rstep] = lo2; }
                        }
                    }
                } else {
                    #pragma unroll
                    for (int r = 0; r < 4; r++) {
                        int i = r * 32 + lane;
                        bool dird = ((i & k) == 0);
                        v[r] = ce_shfl(v[r], j2, dird, lane);
                    }
                }
            }
        }
        #pragma unroll
        for (int r = 0; r < 4; r++) s_key[r * 32 + lane] = v[r];
    }
    __syncthreads();

    u64 v = s_key[t];
    u32 key32 = (u32)(v >> 14);
    int anchor = (int)(0x3FFFu - (u32)(v & 0x3FFF));
    float off = __fmul_rn((float)(c + 1), IMGSZ + 1.0f);
    if (t < n) {
        float4 raw = d_dboxes[(size_t)b * NA + anchor];
        float4 bx;
        bx.x = __fadd_rn(raw.x, off);
        bx.y = __fadd_rn(raw.y, off);
        bx.z = __fadd_rn(raw.z, off);
        bx.w = __fadd_rn(raw.w, off);
        s_bx[t] = bx;
        s_ar[t] = __fmul_rn(__fsub_rn(bx.z, bx.x), __fsub_rn(bx.w, bx.y));
        atomicOr(&s_alive[t >> 6], 1ull << (t & 63));
    }
    __syncthreads();

    if (t < n) {
        float4 bi = s_bx[t];
        float ai = s_ar[t];
        u64 m0 = 0ull, m1 = 0ull;
        for (int j = t + 1; j < n; j++) {
            float4 bj = s_bx[j];
            float lx = fmaxf(bi.x, bj.x), ly = fmaxf(bi.y, bj.y);
            float rx = fminf(bi.z, bj.z), ry = fminf(bi.w, bj.w);
            float iw = fmaxf(__fsub_rn(rx, lx), 0.f);
            float ih = fmaxf(__fsub_rn(ry, ly), 0.f);
            float inter = __fmul_rn(iw, ih);
            bool kill = false;
            if (inter > 0.f) {
                float den = __fadd_rn(__fsub_rn(__fadd_rn(ai, s_ar[j]), inter), 1e-9f);
                kill = (__fdiv_rn(inter, den) > NMS_T);
            }
            if (j < 64) m0 |= ((u64)kill) << j;
            else        m1 |= ((u64)kill) << (j - 64);
        }
        s_m0[t] = m0; s_m1[t] = m1;
        if (m0 | m1) atomicOr(&s_hk[t >> 6], 1ull << (t & 63));
    }
    __syncthreads();

    if (t == 0) {
        u64 a0 = s_alive[0], a1 = s_alive[1];
        #pragma unroll
        for (int w = 0; w < 2; w++) {
            u64 rem = s_hk[w];
            while (rem) {
                int bit = __ffsll((long long)rem) - 1;
                rem &= rem - 1;
                u64 ab = (w == 0) ? a0 : a1;
                if ((ab >> bit) & 1ull) {
                    int i = (w << 6) + bit;
                    a0 &= ~s_m0[i]; a1 &= ~s_m1[i];
                }
            }
        }
        s_alive[0] = a0; s_alive[1] = a1;
    }
    __syncthreads();

    if (t < n) {
        bool al = (s_alive[t >> 6] >> (t & 63)) & 1ull;
        if (al) {
            u64 fk = ((u64)key32 << 21) | ((u64)(0x7Fu - (u32)c) << 14)
                   | (u64)(0x3FFFu - (u32)anchor);
            int p = atomicAdd(&d_finN[b], 1);
            if (p < FINCAP) d_fin[(size_t)b * FINCAP + p] = fk;
            else d_overflow[b] = 1;
        }
    }
}

// ===== Kernel 3: per-image final top-200 (score desc, cls asc, anchor asc) =====
__global__ void __launch_bounds__(1024) k_out_fast(float* __restrict__ out) {
    extern __shared__ u64 s_f[];          // FINCAP u64 = 72 KB
    __shared__ u64 buf[OUTCAP];
    __shared__ int s_cnt, s_n, s_okflag;
    int b = blockIdx.x, t = threadIdx.x;
    int n = min(d_finN[b], FINCAP);
    int R = (n + 1023) >> 10;

    for (int k = 0; k < R; k++) {
        int i = t + (k << 10);
        s_f[i] = (i < n) ? d_fin[(size_t)b * FINCAP + i] : 0ull;
    }
    buf[t] = 0ull;
    __syncthreads();

    u32 tau = TAU_MIN;
    int ovf = d_overflow[b];
    if (n > OUTCAP - 64) {
        u64 lo = (u64)TAU_MIN + 1, hi = 0xBF800000ull;
        int cntb = n;
        while (lo <= hi) {
            u32 mid = (u32)(lo + ((hi - lo) >> 1));
            if (t == 0) s_cnt = 0;
            __syncthreads();
            int cl = 0;
            for (int k = 0; k < R; k++)
                cl += ((u32)(s_f[t + (k << 10)] >> 21) >= mid);
            #pragma unroll
            for (int o = 16; o; o >>= 1) cl += __shfl_down_sync(0xffffffffu, cl, o);
            if ((t & 31) == 0) atomicAdd(&s_cnt, cl);
            __syncthreads();
            int cn = s_cnt;
            __syncthreads();
            if (cn >= MAXDET) {
                tau = mid; cntb = cn; lo = (u64)mid + 1;
                if (cn <= OUTCAP - 64) break;
            } else hi = (u64)mid - 1;
        }
        if (cntb > OUTCAP - 64) ovf = 1;
    }

    if (t == 0) s_n = 0;
    __syncthreads();
    for (int k = 0; k < R; k++) {
        u64 v = s_f[t + (k << 10)];
        if (v != 0ull && (u32)(v >> 21) >= tau) {
            int p = atomicAdd(&s_n, 1);
            if (p < OUTCAP) buf[p] = v;
        }
    }
    __syncthreads();

    for (int k = 2; k <= OUTCAP; k <<= 1) {
        for (int j2 = k >> 1; j2 > 0; j2 >>= 1) {
            int ixj = t ^ j2;
            if (ixj > t) {
                u64 x = buf[t], y = buf[ixj];
                bool sw = ((t & k) == 0) ? (x < y) : (x > y);
                if (sw) { buf[t] = y; buf[ixj] = x; }
            }
            __syncthreads();
        }
    }

    if (t == 0) {
        u64 v199 = buf[MAXDET - 1];
        u32 s200 = (u32)(v199 >> 21);
        int ok = (!ovf) && (s200 > CAPMAX);
        s_okflag = ok;
        d_ok[b] = ok;
        d_finN[b] = 0;                    // self-reset for next replay
        d_overflow[b] = 0;
    }
    __syncthreads();

    if (s_okflag && t < MAXDET) {
        u64 v = buf[t];
        float4 bx = make_float4(0.f, 0.f, 0.f, 0.f);
        float so = 0.f, lb = 0.f;
        if (v != 0ull) {
            u32 key32 = (u32)(v >> 21);
            int cls = (int)(0x7Fu - ((u32)(v >> 14) & 0x7Fu));
            int anchor = (int)(0x3FFFu - (u32)(v & 0x3FFF));
            so = __uint_as_float(key32 ^ 0x80000000u);
            bx = d_dboxes[(size_t)b * NA + anchor];
            lb = (float)(cls + 1);
        }
        size_t ob = ((size_t)b * MAXDET + t) * 4;
        out[ob + 0] = bx.x; out[ob + 1] = bx.y;
        out[ob + 2] = bx.z; out[ob + 3] = bx.w;
        out[(size_t)BATCH * MAXDET * 4 + (size_t)b * MAXDET + t] = so;
        out[(size_t)BATCH * MAXDET * 5 + (size_t)b * MAXDET + t] = lb;
    }
}

// ============== FALLBACK (proven bodies, grid-stride-gated) =================
#define NTILES ((BATCH * NA) / 32)   /* 8732 */

__global__ void __launch_bounds__(1024) k_probs_fb(const float* __restrict__ logits) {
    __shared__ float s_p[NC][33];
    int w = threadIdx.x >> 5, lane = threadIdx.x & 31;

    for (int tile = blockIdx.x; tile < NTILES; tile += gridDim.x) {
        int bA = (tile * 32) / NA;
        int bB = (tile * 32 + 31) / NA;
        if (d_ok[bA] && d_ok[bB]) continue;

        long flat = (long)tile * 32 + w;
        size_t lbase = (size_t)flat * NCLASS;
        int a0 = (int)(tile * 32 - bA * NA);

        float x0 = logits[lbase + lane];
        float x1 = logits[lbase + lane + 32];
        float x2 = (lane < 27) ? logits[lbase + lane + 64] : NEG_INF;

        float m = fmaxf(fmaxf(x0, x1), x2);
        #pragma unroll
        for (int o = 16; o; o >>= 1) m = fmaxf(m, __shfl_down_sync(0xffffffffu, m, o));
        m = __shfl_sync(0xffffffffu, m, 0);

        float e0 = expf(x0 - m), e1 = expf(x1 - m), e2 = expf(x2 - m);
        float s = __fadd_rn(__fadd_rn(e0, e1), e2);
        #pragma unroll
        for (int o = 16; o; o >>= 1) s = __fadd_rn(s, __shfl_down_sync(0xffffffffu, s, o));
        s = __shfl_sync(0xffffffffu, s, 0);

        if (lane >= 1) {
            float p = __fdiv_rn(e0, s);
            s_p[lane - 1][w] = (p > SCORE_T) ? p : NEG_INF;
        }
        {
            float p = __fdiv_rn(e1, s);
            s_p[lane + 31][w] = (p > SCORE_T) ? p : NEG_INF;
        }
        if (lane < 27) {
            float p = __fdiv_rn(e2, s);
            s_p[lane + 63][w] = (p > SCORE_T) ? p : NEG_INF;
        }
        __syncthreads();

        #pragma unroll
        for (int i = threadIdx.x; i < NC * 32; i += 1024) {
            int c = i >> 5, wl = i & 31;
            int a = a0 + wl, b = bA;
            if (a >= NA) { a -= NA; b++; }
            d_probs[((size_t)b * NC + c) * NA + a] = s_p[c][wl];
        }
        __syncthreads();   // protect s_p reuse across iterations
    }
}

#define TKTHREADS 512
#define TKCAP 512
#define NLOC 18

// merged fallback: per-(b,c) top-400 + serial greedy NMS, grid-stride over bc
__global__ void __launch_bounds__(TKTHREADS) k_topknms_fb() {
    __shared__ int s_cnt;
    __shared__ u64 buf[TKCAP];
    __shared__ int s_n;
    __shared__ float  s_sc[KTOP];
    __shared__ float4 s_bx[KTOP];
    __shared__ float  s_ar[KTOP];
    __shared__ int    s_alive[KTOP];
    int t = threadIdx.x;

    for (int bc = blockIdx.x; bc < BATCH * NC; bc += gridDim.x) {
        int b = bc / NC, c = bc % NC;
        if (d_ok[b]) continue;
        const float* sc = &d_probs[(size_t)bc * NA];

        u32 key[NLOC];
        #pragma unroll
        for (int j = 0; j < NLOC; j++) {
            int idx = j * TKTHREADS + t;
            float v = (idx < NA) ? sc[idx] : -1.0f;
            key[j] = (idx < NA && v > SCORE_T) ? fmono(v) : 0u;
        }

        u64 lo = 0xBC23D70Bull, hi = 0xBF800000ull;
        u32 tau = 0;
        while (lo <= hi) {
            u32 mid = (u32)(lo + ((hi - lo) >> 1));
            if (t == 0) s_cnt = 0;
            __syncthreads();
            int cl = 0;
            #pragma unroll
            for (int j = 0; j < NLOC; j++) cl += (key[j] >= mid);
            #pragma unroll
            for (int o = 16; o; o >>= 1) cl += __shfl_down_sync(0xffffffffu, cl, o);
            if ((t & 31) == 0) atomicAdd(&s_cnt, cl);
            __syncthreads();
            int cnt = s_cnt;
            __syncthreads();
            if (cnt >= KTOP) { tau = mid; lo = (u64)mid + 1; }
            else             { hi = (u64)mid - 1; }
        }

        if (t == 0) s_n = 0;
        buf[t] = 0ull;
        __syncthreads();
        #pragma unroll
        for (int j = 0; j < NLOC; j++) {
            if (key[j] != 0u && key[j] >= tau) {
                int p = atomicAdd(&s_n, 1);
                if (p < TKCAP) {
                    u32 anchor = (u32)(j * TKTHREADS + t);
                    buf[p] = ((u64)key[j] << 32) | (u64)(0xFFFFFFFFu - anchor);
                }
            }
        }
        __syncthreads();

        for (int k = 2; k <= TKCAP; k <<= 1) {
            for (int j2 = k >> 1; j2 > 0; j2 >>= 1) {
                int ixj = t ^ j2;
                if (ixj > t) {
                    u64 x = buf[t], y = buf[ixj];
                    bool sw = ((t & k) == 0) ? (x < y) : (x > y);
                    if (sw) { buf[t] = y; buf[ixj] = x; }
                }
                __syncthreads();
            }
        }

        int nv = min(s_n, TKCAP);
        float off = __fmul_rn((float)(c + 1), IMGSZ + 1.0f);

        float4 my = make_float4(0.f, 0.f, 0.f, 0.f);
        float mya = 0.f;
        int myanc = 0;
        if (t < KTOP) {
            float scv = NEG_INF;
            int anc = 0;
            if (t < nv) {
                u64 v = buf[t];
                u32 h32 = (u32)(v >> 32);
                scv = __uint_as_float(h32 ^ 0x80000000u);
                anc = (int)(0xFFFFFFFFu - (u32)v);
            }
            myanc = anc;
            float4 raw = d_dboxes[(size_t)b * NA + anc];
            float4 bx;
            bx.x = __fadd_rn(raw.x, off);
            bx.y = __fadd_rn(raw.y, off);
            bx.z = __fadd_rn(raw.z, off);
            bx.w = __fadd_rn(raw.w, off);
            s_sc[t] = scv;
            s_bx[t] = bx;
            float ar = __fmul_rn(__fsub_rn(bx.z, bx.x), __fsub_rn(bx.w, bx.y));
            s_ar[t] = ar;
            s_alive[t] = isfinite(scv) ? 1 : 0;
            my = bx; mya = ar;
        }
        __syncthreads();

        for (int i = 0; i < KTOP; i++) {
            if (s_alive[i]) {
                if (t > i && t < KTOP && s_alive[t]) {
                    float4 bi = s_bx[i];
                    float lx = fmaxf(bi.x, my.x), ly = fmaxf(bi.y, my.y);
                    float rx = fminf(bi.z, my.z), ry = fminf(bi.w, my.w);
                    float iw = fmaxf(__fsub_rn(rx, lx), 0.f);
                    float ih = fmaxf(__fsub_rn(ry, ly), 0.f);
                    float inter = __fmul_rn(iw, ih);
                    float den = __fadd_rn(__fsub_rn(__fadd_rn(s_ar[i], mya), inter), 1e-9f);
                    float iou = __fdiv_rn(inter, den);
                    if (iou > NMS_T) s_alive[t] = 0;
                }
                __syncthreads();
            }
        }
        __syncthreads();
        if (t < KTOP) {
            size_t obase = (size_t)b * NCAND + (size_t)c * KTOP;
            d_candScore[obase + t]  = s_alive[t] ? s_sc[t] : NEG_INF;
            d_candAnchor[obase + t] = myanc;
        }
        __syncthreads();   // protect shared reuse across iterations
    }
}

#define SELPAD 36864
__global__ void __launch_bounds__(1024) k_select_fb(float* __restrict__ out) {
    int b = blockIdx.x, t = threadIdx.x;
    if (d_ok[b]) return;
    extern __shared__ u32 s_key2[];
    __shared__ u64 buf[512];
    __shared__ int s_cnt, s_n;

    for (int i = t; i < NCAND; i += 1024) {
        float v = d_candScore[(size_t)b * NCAND + i];
        s_key2[i] = isfinite(v) ? fmono(v) : 0u;
    }
    for (int i = NCAND + t; i < SELPAD; i += 1024) s_key2[i] = 0u;
    if (t < 512) buf[t] = 0ull;

    u64 lo = 0xBC23D70Bull, hi = 0xBF800000ull;
    u32 tau = 0;
    const uint4* k4 = (const uint4*)s_key2;
    __syncthreads();
    while (lo <= hi) {
        u32 mid = (u32)(lo + ((hi - lo) >> 1));
        if (t == 0) s_cnt = 0;
        __syncthreads();
        int cl = 0;
        #pragma unroll
        for (int k = 0; k < 9; k++) {
            uint4 v = k4[t + (k << 10)];
            cl += (v.x >= mid) + (v.y >= mid) + (v.z >= mid) + (v.w >= mid);
        }
        #pragma unroll
        for (int o = 16; o; o >>= 1) cl += __shfl_down_sync(0xffffffffu, cl, o);
        if ((t & 31) == 0) atomicAdd(&s_cnt, cl);
        __syncthreads();
        int cnt = s_cnt;
        __syncthreads();
        if (cnt >= MAXDET) { tau = mid; lo = (u64)mid + 1; }
        else               { hi = (u64)mid - 1; }
    }
    if (t == 0) s_n = 0;
    __syncthreads();
    #pragma unroll
    for (int k = 0; k < 36; k++) {
        int i = t + (k << 10);
        if (i < NCAND) {
            u32 kv = s_key2[i];
            if (kv >= tau) {
                int p = atomicAdd(&s_n, 1);
                if (p < 512)
                    buf[p] = ((u64)kv << 32) | (u64)(0xFFFFFFFFu - (u32)i);
            }
        }
    }
    __syncthreads();

    for (int k = 2; k <= 512; k <<= 1) {
        for (int j2 = k >> 1; j2 > 0; j2 >>= 1) {
            if (t < 512) {
                int ixj = t ^ j2;
                if (ixj > t) {
                    u64 x = buf[t], y = buf[ixj];
                    bool sw = ((t & k) == 0) ? (x < y) : (x > y);
                    if (sw) { buf[t] = y; buf[ixj] = x; }
                }
            }
            __syncthreads();
        }
    }

    if (t < MAXDET) {
        u64 v = buf[t];
        u32 h = (u32)(v >> 32);
        float4 bx = make_float4(0.f, 0.f, 0.f, 0.f);
        float so = 0.f, lb = 0.f;
        if (h != 0u) {
            int idx = (int)(0xFFFFFFFFu - (u32)v);
            so = __uint_as_float(h ^ 0x80000000u);
            int cls = idx / KTOP;
            int anc = d_candAnchor[(size_t)b * NCAND + idx];
            bx = d_dboxes[(size_t)b * NA + anc];
            lb = (float)(cls + 1);
        }
        size_t ob = ((size_t)b * MAXDET + t) * 4;
        out[ob + 0] = bx.x; out[ob + 1] = bx.y;
        out[ob + 2] = bx.z; out[ob + 3] = bx.w;
        out[(size_t)BATCH * MAXDET * 4 + (size_t)b * MAXDET + t] = so;
        out[(size_t)BATCH * MAXDET * 5 + (size_t)b * MAXDET + t] = lb;
    }
}

// ================= host =================
extern "C" void kernel_launch(void* const* d_in, const int* in_sizes, int n_in,
                              void* d_out, int out_size) {
    const float* logits  = (const float*)d_in[0];
    const float* reg     = (const float*)d_in[1];
    const float* anchors = (const float*)d_in[2];
    float* out = (float*)d_out;

    k_softmax_decode<<<(BATCH * NA) / 32, 1024>>>(logits, reg, anchors);
    k_nms_fast<<<BATCH * NC, 128>>>();
    cudaFuncSetAttribute(k_out_fast, cudaFuncAttributeMaxDynamicSharedMemorySize,
                         FINCAP * (int)sizeof(u64));
    k_out_fast<<<BATCH, 1024, FINCAP * sizeof(u64)>>>(out);
    // fallback chain (cheap grid-stride no-ops when fast path verified exact)
    k_probs_fb<<<512, 1024>>>(logits);
    k_topknms_fb<<<480, TKTHREADS>>>();
    cudaFuncSetAttribute(k_select_fb, cudaFuncAttributeMaxDynamicSharedMemorySize,
                         SELPAD * (int)sizeof(u32));
    k_select_fb<<<BATCH, 1024, SELPAD * sizeof(u32)>>>(out);
}